// round 12
// baseline (speedup 1.0000x reference)
#include <cuda_runtime.h>
#include <cuda_fp16.h>
#include <math.h>
#include <stdint.h>

#define B_ 4
#define N_ 2048
#define C_ 1024
#define M_TOT (B_ * N_)   // 8192

// ---------------- scratch (__device__ globals; no allocation) ----------------
__device__ __align__(128) __half g_hh[(size_t)M_TOT * C_];
__device__ __align__(128) __half g_Wvh[C_ * C_];
__device__ __align__(128) __half g_WqT[C_ * C_];
__device__ __align__(128) __half g_WkT[C_ * C_];
__device__ __align__(128) __half g_MT[C_ * C_];
__device__ __align__(128) __half g_QM[(size_t)M_TOT * C_];
__device__ __align__(128) __half g_VT[(size_t)C_ * M_TOT];
__device__ __align__(128) __half g_P[(size_t)B_ * N_ * N_];
__device__ float g_w1p[8][C_], g_w2p[8][C_];
__device__ float g_u32[M_TOT], g_v32[M_TOT];
__device__ float g_cc;

// ---------------- portable PTX helpers ----------------
__device__ __forceinline__ uint32_t smem_u32(const void* p) {
    uint32_t a;
    asm("{ .reg .u64 t; cvta.to.shared.u64 t, %1; cvt.u32.u64 %0, t; }" : "=r"(a) : "l"(p));
    return a;
}
__device__ __forceinline__ void cp_async16(uint32_t dst, const void* src) {
    asm volatile("cp.async.cg.shared.global [%0], [%1], 16;" :: "r"(dst), "l"(src) : "memory");
}
#define CP_COMMIT()  asm volatile("cp.async.commit_group;" ::: "memory")
#define CP_WAIT(n)   asm volatile("cp.async.wait_group %0;" :: "n"(n) : "memory")

__device__ __forceinline__ void ldsm_x4(uint32_t& r0, uint32_t& r1, uint32_t& r2, uint32_t& r3,
                                        uint32_t addr) {
    asm volatile("ldmatrix.sync.aligned.m8n8.x4.shared.b16 {%0,%1,%2,%3}, [%4];"
                 : "=r"(r0), "=r"(r1), "=r"(r2), "=r"(r3) : "r"(addr));
}
__device__ __forceinline__ void mma16816(float* d, const uint32_t* a, const uint32_t* b) {
    asm volatile(
        "mma.sync.aligned.m16n8k16.row.col.f32.f16.f16.f32 "
        "{%0,%1,%2,%3}, {%4,%5,%6,%7}, {%8,%9}, {%0,%1,%2,%3};"
        : "+f"(d[0]), "+f"(d[1]), "+f"(d[2]), "+f"(d[3])
        : "r"(a[0]), "r"(a[1]), "r"(a[2]), "r"(a[3]), "r"(b[0]), "r"(b[1]));
}
__device__ __forceinline__ uint32_t swz(uint32_t off) { return off ^ ((off >> 3) & 0x70); }

// ---------------- templated segmented fp16 GEMM: D = alpha*(A @ B^T) (+bias) -------------
// Block tile 128 x BN, BK=64 (128B rows); 8 warps 2(m) x 4(n), warp tile 64 x (BN/4).
#define BM_ 128
#define STAGES 3
#define TILE_A_BYTES 16384

struct GemmSeg {
    const __half* A; const __half* B;
    long long batA, batB, batC;
    int lda, ldb, ldc, K;
    float* Cf; __half* Ch;
    float alpha;
    const float* bias; int bias_mode;
    int gx, gxy;
};

template <int BN>
__global__ __launch_bounds__(256, 1) void gemm_seg_t(GemmSeg s0, GemmSeg s1, int n0cnt)
{
    constexpr int TILE_B = BN * 128;
    constexpr int STAGE_B = TILE_A_BYTES + TILE_B;
    constexpr int NT = BN / 32;          // n-subtiles (8-wide) per warp
    constexpr int NLD = BN / 64;         // ldsm_x4 count for B per k16

    extern __shared__ char smem[];
    const uint32_t sbase = smem_u32(smem);
    const int tid  = threadIdx.x;
    const int wid  = tid >> 5;
    const int lane = tid & 31;

    const bool f = (int)blockIdx.x < n0cnt;
    const __half* Ag = f ? s0.A : s1.A;
    const __half* Bg = f ? s0.B : s1.B;
    const long long batA = f ? s0.batA : s1.batA;
    const long long batB = f ? s0.batB : s1.batB;
    const long long batC = f ? s0.batC : s1.batC;
    const int lda = f ? s0.lda : s1.lda;
    const int ldb = f ? s0.ldb : s1.ldb;
    const int ldc = f ? s0.ldc : s1.ldc;
    const int K   = f ? s0.K   : s1.K;
    float* Cf = f ? s0.Cf : s1.Cf;
    __half* Ch = f ? s0.Ch : s1.Ch;
    const float alpha = f ? s0.alpha : s1.alpha;
    const float* bias = f ? s0.bias : s1.bias;
    const int bias_mode = f ? s0.bias_mode : s1.bias_mode;
    const int gx  = f ? s0.gx  : s1.gx;
    const int gxy = f ? s0.gxy : s1.gxy;

    int lid = blockIdx.x - (f ? 0 : n0cnt);
    const long long bz = lid / gxy;
    int r = lid - (int)bz * gxy;
    const int m0 = (r / gx) * BM_;
    const int n0 = (r % gx) * BN;

    const __half* Ap = Ag + bz * batA;
    const __half* Bp = Bg + bz * batB;

    const int wm = (wid >> 2) * 64;
    const int wn = (wid & 3) * (BN / 4);

    const int NK = K >> 6;

    const int lrow = tid >> 3;
    const int lch  = tid & 7;

    auto load_stage = [&](int kc, int s) {
        const __half* Asrc = Ap + (size_t)m0 * lda + kc * 64;
        const __half* Bsrc = Bp + (size_t)n0 * ldb + kc * 64;
        const uint32_t sa = sbase + s * STAGE_B;
        const uint32_t sb = sa + TILE_A_BYTES;
        #pragma unroll
        for (int rr = 0; rr < 4; rr++) {
            int row = rr * 32 + lrow;
            uint32_t sw = swz(row * 128 + lch * 16);
            cp_async16(sa + sw, Asrc + (size_t)row * lda + lch * 8);
        }
        #pragma unroll
        for (int rr = 0; rr < BN / 32; rr++) {
            int row = rr * 32 + lrow;
            uint32_t sw = swz(row * 128 + lch * 16);
            cp_async16(sb + sw, Bsrc + (size_t)row * ldb + lch * 8);
        }
        CP_COMMIT();
    };

    float acc[4][NT][4];
    #pragma unroll
    for (int i = 0; i < 4; i++)
        #pragma unroll
        for (int j = 0; j < NT; j++)
            #pragma unroll
            for (int e = 0; e < 4; e++) acc[i][j][e] = 0.f;

    const int a_row_l = ((lane >> 3) & 1) * 8 + (lane & 7);
    const int a_col_l = ((lane >> 4) & 1) * 16;
    const int b_row_l = ((lane >> 4) & 1) * 8 + (lane & 7);
    const int b_col_l = ((lane >> 3) & 1) * 16;

    #pragma unroll
    for (int i = 0; i < STAGES; i++)
        if (i < NK) load_stage(i, i);

    int s = 0;
    for (int kc = 0; kc < NK; kc++) {
        int rem = NK - 1 - kc;
        if (rem >= 2)      { CP_WAIT(2); }
        else if (rem == 1) { CP_WAIT(1); }
        else               { CP_WAIT(0); }
        __syncthreads();

        const uint32_t cur_sa = sbase + s * STAGE_B;
        const uint32_t cur_sb = cur_sa + TILE_A_BYTES;

        #pragma unroll
        for (int k16 = 0; k16 < 4; k16++) {
            uint32_t a[4][4], b[NT][2];
            #pragma unroll
            for (int mt = 0; mt < 4; mt++) {
                uint32_t off = (uint32_t)(wm + mt * 16 + a_row_l) * 128 + k16 * 32 + a_col_l;
                ldsm_x4(a[mt][0], a[mt][1], a[mt][2], a[mt][3], cur_sa + swz(off));
            }
            #pragma unroll
            for (int nt2 = 0; nt2 < NLD; nt2++) {
                uint32_t off = (uint32_t)(wn + nt2 * 16 + b_row_l) * 128 + k16 * 32 + b_col_l;
                uint32_t r0, r1, r2, r3;
                ldsm_x4(r0, r1, r2, r3, cur_sb + swz(off));
                b[nt2 * 2 + 0][0] = r0; b[nt2 * 2 + 0][1] = r1;
                b[nt2 * 2 + 1][0] = r2; b[nt2 * 2 + 1][1] = r3;
            }
            #pragma unroll
            for (int mt = 0; mt < 4; mt++)
                #pragma unroll
                for (int nt = 0; nt < NT; nt++)
                    mma16816(acc[mt][nt], a[mt], b[nt]);
        }

        __syncthreads();
        if (kc + STAGES < NK) load_stage(kc + STAGES, s);
        s++;
        if (s == STAGES) s = 0;
    }

    const int erow = lane >> 2;
    const int ecol = (lane & 3) * 2;

    #pragma unroll
    for (int mt = 0; mt < 4; mt++) {
        #pragma unroll
        for (int h = 0; h < 2; h++) {
            const int gm = m0 + wm + mt * 16 + h * 8 + erow;
            float brow = (bias_mode == 2) ? bias[gm] : 0.f;
            #pragma unroll
            for (int nt = 0; nt < NT; nt++) {
                const int gn = n0 + wn + nt * 8 + ecol;
                float x0 = acc[mt][nt][h * 2 + 0] * alpha;
                float x1 = acc[mt][nt][h * 2 + 1] * alpha;
                if (bias_mode == 1) { x0 += bias[gn]; x1 += bias[gn + 1]; }
                else if (bias_mode == 2) { x0 += brow; x1 += brow; }
                if (Cf) {
                    float2 v; v.x = x0; v.y = x1;
                    *(float2*)(Cf + bz * batC + (size_t)gm * ldc + gn) = v;
                } else {
                    __half2 hv = __floats2half2_rn(x0, x1);
                    *(__half2*)(Ch + bz * batC + (size_t)gm * ldc + gn) = hv;
                }
            }
        }
    }
}

// ---------------- elementwise / small kernels ----------------
__global__ __launch_bounds__(256) void cast_fp16_2(
    const float* __restrict__ x0, __half* __restrict__ y0,
    const float* __restrict__ x1, __half* __restrict__ y1, int n0)
{
    const bool f = (int)blockIdx.x < n0;
    const float* x = f ? x0 : x1;
    __half* y = f ? y0 : y1;
    size_t i = ((size_t)(f ? blockIdx.x : blockIdx.x - n0) * 256 + threadIdx.x);
    float4 v = *(const float4*)(x + i * 4);
    __half2 h0 = __floats2half2_rn(v.x, v.y);
    __half2 h1 = __floats2half2_rn(v.z, v.w);
    uint2 u;
    u.x = *(uint32_t*)&h0;
    u.y = *(uint32_t*)&h1;
    *(uint2*)(y + i * 4) = u;
}

__global__ __launch_bounds__(256) void tcast2(
    const float* __restrict__ Wq, const float* __restrict__ Wk,
    __half* __restrict__ oq, __half* __restrict__ ok)
{
    __shared__ __half tile[32][33];
    const float* in = blockIdx.z ? Wk : Wq;
    __half* out = blockIdx.z ? ok : oq;
    const int bx = blockIdx.x * 32;
    const int by = blockIdx.y * 32;
    const int tx = threadIdx.x & 31;
    const int ty = threadIdx.x >> 5;
    #pragma unroll
    for (int i = 0; i < 32; i += 8)
        tile[ty + i][tx] = __float2half(in[(size_t)(by + ty + i) * C_ + bx + tx]);
    __syncthreads();
    #pragma unroll
    for (int i = 0; i < 32; i += 8)
        out[(size_t)(bx + ty + i) * C_ + by + tx] = tile[tx][ty + i];
}

__global__ __launch_bounds__(256) void wvec_p(
    const float* __restrict__ Wq, const float* __restrict__ Wk,
    const float* __restrict__ bq, const float* __restrict__ bk)
{
    const int bid = blockIdx.x;
    if (bid < 64) {
        const bool isq = bid < 32;
        const float* W = isq ? Wq : Wk;
        const float* bb = isq ? bk : bq;
        float* dst = isq ? &g_w1p[0][0] : &g_w2p[0][0];
        int lb = isq ? bid : bid - 32;
        int c = (lb & 3) * 256 + threadIdx.x;
        int dchunk = lb >> 2;
        float s = 0.f;
        #pragma unroll 4
        for (int d = dchunk * 128; d < dchunk * 128 + 128; d++)
            s += W[(size_t)d * C_ + c] * bb[d];
        dst[dchunk * C_ + c] = s;
    } else {
        const int tid = threadIdx.x;
        float s = 0.f;
        for (int d = tid; d < C_; d += 256) s += bq[d] * bk[d];
        __shared__ float red[8];
        #pragma unroll
        for (int off = 16; off > 0; off >>= 1)
            s += __shfl_xor_sync(0xffffffffu, s, off);
        if ((tid & 31) == 0) red[tid >> 5] = s;
        __syncthreads();
        if (tid == 0) {
            float t = 0.f;
            for (int w = 0; w < 8; w++) t += red[w];
            g_cc = t;
        }
    }
}

// u32[i] = (h_i.w1 + cc)/32 ; v32[i] = (h_i.w2)/32 ; 32 rows per block (4 per warp)
__global__ __launch_bounds__(256) void uvvec(const __half* __restrict__ hh)
{
    __shared__ float w1s[C_], w2s[C_];
    const int tid = threadIdx.x;
    for (int i = tid; i < C_; i += 256) {
        float s1 = 0.f, s2 = 0.f;
        #pragma unroll
        for (int p = 0; p < 8; p++) { s1 += g_w1p[p][i]; s2 += g_w2p[p][i]; }
        w1s[i] = s1; w2s[i] = s2;
    }
    __syncthreads();
    const int lane = tid & 31;
    const int warp = tid >> 5;
    #pragma unroll
    for (int rr = 0; rr < 4; rr++) {
        const int row = blockIdx.x * 32 + warp * 4 + rr;
        const __half2* hr = (const __half2*)(hh + (size_t)row * C_);
        float s1 = 0.f, s2 = 0.f;
        #pragma unroll
        for (int k = 0; k < 16; k++) {
            int idx = lane + k * 32;
            float2 fv = __half22float2(hr[idx]);
            s1 += fv.x * w1s[2 * idx] + fv.y * w1s[2 * idx + 1];
            s2 += fv.x * w2s[2 * idx] + fv.y * w2s[2 * idx + 1];
        }
        #pragma unroll
        for (int off = 16; off > 0; off >>= 1) {
            s1 += __shfl_xor_sync(0xffffffffu, s1, off);
            s2 += __shfl_xor_sync(0xffffffffu, s2, off);
        }
        if (lane == 0) {
            g_u32[row] = (s1 + g_cc) * (1.0f / 32.0f);
            g_v32[row] = s2 * (1.0f / 32.0f);
        }
    }
}

__global__ __launch_bounds__(256) void softmax_h(
    float* __restrict__ P, __half* __restrict__ Ph)
{
    const size_t row = blockIdx.x;
    float* p = P + row * (size_t)N_;
    __half* ph = Ph + row * (size_t)N_;
    const float* vb = g_v32 + (row >> 11 << 11);
    const float uadd = g_u32[row];
    const int tid = threadIdx.x;
    const int lane = tid & 31;
    const int warp = tid >> 5;

    float vals[8];
    float m = -INFINITY;
    #pragma unroll
    for (int i = 0; i < 8; i++) {
        int j = tid + i * 256;
        vals[i] = p[j] + uadd + vb[j];
        m = fmaxf(m, vals[i]);
    }
    __shared__ float redmax[8], redsum[8];
    #pragma unroll
    for (int off = 16; off > 0; off >>= 1)
        m = fmaxf(m, __shfl_xor_sync(0xffffffffu, m, off));
    if (lane == 0) redmax[warp] = m;
    __syncthreads();
    float rowmax = redmax[0];
    #pragma unroll
    for (int w = 1; w < 8; w++) rowmax = fmaxf(rowmax, redmax[w]);

    float sum = 0.f;
    #pragma unroll
    for (int i = 0; i < 8; i++) {
        vals[i] = __expf(vals[i] - rowmax);
        sum += vals[i];
    }
    #pragma unroll
    for (int off = 16; off > 0; off >>= 1)
        sum += __shfl_xor_sync(0xffffffffu, sum, off);
    if (lane == 0) redsum[warp] = sum;
    __syncthreads();
    float total = 0.f;
    #pragma unroll
    for (int w = 0; w < 8; w++) total += redsum[w];
    float inv = 1.f / total;

    #pragma unroll
    for (int i = 0; i < 8; i++) {
        float v = vals[i] * inv;
        p[tid + i * 256] = v;
        ph[tid + i * 256] = __float2half(v);
    }
}

// ---------------- launch ----------------
extern "C" void kernel_launch(void* const* d_in, const int* in_sizes, int n_in,
                              void* d_out, int out_size)
{
    const float* h  = (const float*)d_in[0];
    const float* Wq = (const float*)d_in[1];
    const float* bq = (const float*)d_in[2];
    const float* Wk = (const float*)d_in[3];
    const float* bk = (const float*)d_in[4];
    const float* Wv = (const float*)d_in[5];
    const float* bv = (const float*)d_in[6];

    float* out  = (float*)d_out;
    float* attn = out + (size_t)B_ * N_ * C_;

    __half *hh, *Wvh, *WqT, *WkT, *MT, *QM, *VT, *P;
    cudaGetSymbolAddress((void**)&hh,  g_hh);
    cudaGetSymbolAddress((void**)&Wvh, g_Wvh);
    cudaGetSymbolAddress((void**)&WqT, g_WqT);
    cudaGetSymbolAddress((void**)&WkT, g_WkT);
    cudaGetSymbolAddress((void**)&MT,  g_MT);
    cudaGetSymbolAddress((void**)&QM,  g_QM);
    cudaGetSymbolAddress((void**)&VT,  g_VT);
    cudaGetSymbolAddress((void**)&P,   g_P);

    const int SMEM256 = STAGES * (TILE_A_BYTES + 256 * 128);   // 144 KB
    const int SMEM128 = STAGES * (TILE_A_BYTES + 128 * 128);   // 96 KB
    cudaFuncSetAttribute(gemm_seg_t<256>, cudaFuncAttributeMaxDynamicSharedMemorySize, SMEM256);
    cudaFuncSetAttribute(gemm_seg_t<128>, cudaFuncAttributeMaxDynamicSharedMemorySize, SMEM128);

    // 1) casts / transposes / bias partials
    {
        int nh = (int)((size_t)M_TOT * C_ / 4 / 256);
        int nw = (int)((size_t)C_ * C_ / 4 / 256);
        cast_fp16_2<<<nh + nw, 256>>>(h, hh, Wv, Wvh, nh);
        dim3 tg(C_ / 32, C_ / 32, 2);
        tcast2<<<tg, 256>>>(Wq, Wk, WqT, WkT);
        wvec_p<<<65, 256>>>(Wq, Wk, bq, bk);
        uvvec<<<M_TOT / 32, 256>>>(hh);
    }

    auto mkseg = [](const __half* A, const __half* B, long long bA, long long bB,
                    long long bC, int lda, int ldb, int ldc, int K,
                    float* Cf, __half* Ch, float alpha,
                    const float* bias, int bias_mode, int gx, int gy) {
        GemmSeg s;
        s.A = A; s.B = B; s.batA = bA; s.batB = bB; s.batC = bC;
        s.lda = lda; s.ldb = ldb; s.ldc = ldc; s.K = K;
        s.Cf = Cf; s.Ch = Ch; s.alpha = alpha; s.bias = bias; s.bias_mode = bias_mode;
        s.gx = gx; s.gxy = gx * gy;
        return s;
    };

    // 2) merged: VT = Wvh @ hh^T + bv (row bias) [256] ; MT = WkT @ WqT^T [32]
    {
        GemmSeg sVT = mkseg(Wvh, hh, 0, 0, 0, C_, C_, M_TOT, C_,
                            nullptr, VT, 1.0f, bv, 2, M_TOT / 256, C_ / BM_);
        GemmSeg sMT = mkseg(WkT, WqT, 0, 0, 0, C_, C_, C_, C_,
                            nullptr, MT, 1.0f, nullptr, 0, C_ / 256, C_ / BM_);
        int n0 = (M_TOT / 256) * (C_ / BM_);
        int n1 = (C_ / 256) * (C_ / BM_);
        gemm_seg_t<256><<<n0 + n1, 256, SMEM256>>>(sVT, sMT, n0);
    }
    // 3) QM = hh @ MT^T  [256 CTAs, 128x256]
    {
        GemmSeg s = mkseg(hh, MT, 0, 0, 0, C_, C_, C_, C_,
                          nullptr, QM, 1.0f, nullptr, 0, C_ / 256, M_TOT / BM_);
        gemm_seg_t<256><<<s.gxy, 256, SMEM256>>>(s, s, s.gxy);
    }
    // 4) scores = (QM_b @ hh_b^T)/32 -> fp32 attn  [1024 CTAs, 128x128 for packing]
    {
        GemmSeg s = mkseg(QM, hh, (long long)N_ * C_, (long long)N_ * C_,
                          (long long)N_ * N_, C_, C_, N_, C_,
                          attn, nullptr, 1.0f / 32.0f, nullptr, 0, N_ / 128, N_ / BM_);
        int n = s.gxy * B_;
        gemm_seg_t<128><<<n, 256, SMEM128>>>(s, s, n);
    }
    // 5) softmax + fp16 P
    softmax_h<<<B_ * N_, 256>>>(attn, P);

    // 6) out = P_b @ VT_b^T  [256 CTAs, 128x256, K=2048]
    {
        GemmSeg s = mkseg(P, VT, (long long)N_ * N_, (long long)N_,
                          (long long)N_ * C_, N_, M_TOT, C_, N_,
                          out, nullptr, 1.0f, nullptr, 0, C_ / 256, N_ / BM_);
        int n = s.gxy * B_;
        gemm_seg_t<256><<<n, 256, SMEM256>>>(s, s, n);
    }
}

// round 13
// speedup vs baseline: 1.0085x; 1.0085x over previous
#include <cuda_runtime.h>
#include <cuda_fp16.h>
#include <math.h>
#include <stdint.h>

#define B_ 4
#define N_ 2048
#define C_ 1024
#define M_TOT (B_ * N_)   // 8192

// ---------------- scratch (__device__ globals; no allocation) ----------------
__device__ __align__(128) __half g_hh[(size_t)M_TOT * C_];
__device__ __align__(128) __half g_Wvh[C_ * C_];
__device__ __align__(128) __half g_WqT[C_ * C_];
__device__ __align__(128) __half g_WkT[C_ * C_];
__device__ __align__(128) __half g_MT[C_ * C_];
__device__ __align__(128) __half g_QM[(size_t)M_TOT * C_];
__device__ __align__(128) __half g_VT[(size_t)C_ * M_TOT];
__device__ __align__(128) __half g_P[(size_t)B_ * N_ * N_];
__device__ float g_w1p[8][C_], g_w2p[8][C_];
__device__ float g_w1[C_], g_w2[C_];
__device__ float g_u32[M_TOT], g_v32[M_TOT];
__device__ float g_cc;

// ---------------- portable PTX helpers ----------------
__device__ __forceinline__ uint32_t smem_u32(const void* p) {
    uint32_t a;
    asm("{ .reg .u64 t; cvta.to.shared.u64 t, %1; cvt.u32.u64 %0, t; }" : "=r"(a) : "l"(p));
    return a;
}
__device__ __forceinline__ void cp_async16(uint32_t dst, const void* src) {
    asm volatile("cp.async.cg.shared.global [%0], [%1], 16;" :: "r"(dst), "l"(src) : "memory");
}
#define CP_COMMIT()  asm volatile("cp.async.commit_group;" ::: "memory")
#define CP_WAIT(n)   asm volatile("cp.async.wait_group %0;" :: "n"(n) : "memory")

__device__ __forceinline__ void ldsm_x4(uint32_t& r0, uint32_t& r1, uint32_t& r2, uint32_t& r3,
                                        uint32_t addr) {
    asm volatile("ldmatrix.sync.aligned.m8n8.x4.shared.b16 {%0,%1,%2,%3}, [%4];"
                 : "=r"(r0), "=r"(r1), "=r"(r2), "=r"(r3) : "r"(addr));
}
__device__ __forceinline__ void mma16816(float* d, const uint32_t* a, const uint32_t* b) {
    asm volatile(
        "mma.sync.aligned.m16n8k16.row.col.f32.f16.f16.f32 "
        "{%0,%1,%2,%3}, {%4,%5,%6,%7}, {%8,%9}, {%0,%1,%2,%3};"
        : "+f"(d[0]), "+f"(d[1]), "+f"(d[2]), "+f"(d[3])
        : "r"(a[0]), "r"(a[1]), "r"(a[2]), "r"(a[3]), "r"(b[0]), "r"(b[1]));
}
__device__ __forceinline__ uint32_t swz(uint32_t off) { return off ^ ((off >> 3) & 0x70); }

// ---------------- segmented fp16 GEMM: D = alpha*(A @ B^T) (+bias) ----------------
// Block tile 128x256, BK=64; 8 warps 2(m)x4(n), warp tile 64x64.
#define BM_ 128
#define BN_ 256
#define STAGES 3
#define TILE_A_BYTES 16384
#define STAGE_BYTES  49152
#define SMEM_GEMM (STAGES * STAGE_BYTES)   // 144 KB

struct GemmSeg {
    const __half* A; const __half* B;
    long long batA, batB, batC;
    int lda, ldb, ldc, K;
    float* Cf; __half* Ch;
    float alpha;
    const float* bias; int bias_mode;
    int gx, gxy;
};

__global__ __launch_bounds__(256, 1) void gemm_seg(GemmSeg s0, GemmSeg s1, int n0cnt)
{
    extern __shared__ char smem[];
    const uint32_t sbase = smem_u32(smem);
    const int tid  = threadIdx.x;
    const int wid  = tid >> 5;
    const int lane = tid & 31;

    const bool f = (int)blockIdx.x < n0cnt;
    const __half* Ag = f ? s0.A : s1.A;
    const __half* Bg = f ? s0.B : s1.B;
    const long long batA = f ? s0.batA : s1.batA;
    const long long batB = f ? s0.batB : s1.batB;
    const long long batC = f ? s0.batC : s1.batC;
    const int lda = f ? s0.lda : s1.lda;
    const int ldb = f ? s0.ldb : s1.ldb;
    const int ldc = f ? s0.ldc : s1.ldc;
    const int K   = f ? s0.K   : s1.K;
    float* Cf = f ? s0.Cf : s1.Cf;
    __half* Ch = f ? s0.Ch : s1.Ch;
    const float alpha = f ? s0.alpha : s1.alpha;
    const float* bias = f ? s0.bias : s1.bias;
    const int bias_mode = f ? s0.bias_mode : s1.bias_mode;
    const int gx  = f ? s0.gx  : s1.gx;
    const int gxy = f ? s0.gxy : s1.gxy;

    int lid = blockIdx.x - (f ? 0 : n0cnt);
    const long long bz = lid / gxy;
    int r = lid - (int)bz * gxy;
    const int m0 = (r / gx) * BM_;
    const int n0 = (r % gx) * BN_;

    const __half* Ap = Ag + bz * batA;
    const __half* Bp = Bg + bz * batB;

    const int wm = (wid >> 2) * 64;
    const int wn = (wid & 3) * 64;

    const int NK = K >> 6;

    const int lrow = tid >> 3;
    const int lch  = tid & 7;

    auto load_stage = [&](int kc, int s) {
        const __half* Asrc = Ap + (size_t)m0 * lda + kc * 64;
        const __half* Bsrc = Bp + (size_t)n0 * ldb + kc * 64;
        const uint32_t sa = sbase + s * STAGE_BYTES;
        const uint32_t sb = sa + TILE_A_BYTES;
        #pragma unroll
        for (int rr = 0; rr < 4; rr++) {
            int row = rr * 32 + lrow;
            uint32_t sw = swz(row * 128 + lch * 16);
            cp_async16(sa + sw, Asrc + (size_t)row * lda + lch * 8);
        }
        #pragma unroll
        for (int rr = 0; rr < 8; rr++) {
            int row = rr * 32 + lrow;
            uint32_t sw = swz(row * 128 + lch * 16);
            cp_async16(sb + sw, Bsrc + (size_t)row * ldb + lch * 8);
        }
        CP_COMMIT();
    };

    float acc[4][8][4];
    #pragma unroll
    for (int i = 0; i < 4; i++)
        #pragma unroll
        for (int j = 0; j < 8; j++)
            #pragma unroll
            for (int e = 0; e < 4; e++) acc[i][j][e] = 0.f;

    const int a_row_l = ((lane >> 3) & 1) * 8 + (lane & 7);
    const int a_col_l = ((lane >> 4) & 1) * 16;
    const int b_row_l = ((lane >> 4) & 1) * 8 + (lane & 7);
    const int b_col_l = ((lane >> 3) & 1) * 16;

    #pragma unroll
    for (int i = 0; i < STAGES; i++)
        if (i < NK) load_stage(i, i);

    int s = 0;
    for (int kc = 0; kc < NK; kc++) {
        int rem = NK - 1 - kc;
        if (rem >= 2)      { CP_WAIT(2); }
        else if (rem == 1) { CP_WAIT(1); }
        else               { CP_WAIT(0); }
        __syncthreads();

        const uint32_t cur_sa = sbase + s * STAGE_BYTES;
        const uint32_t cur_sb = cur_sa + TILE_A_BYTES;

        #pragma unroll
        for (int k16 = 0; k16 < 4; k16++) {
            uint32_t a[4][4], b[8][2];
            #pragma unroll
            for (int mt = 0; mt < 4; mt++) {
                uint32_t off = (uint32_t)(wm + mt * 16 + a_row_l) * 128 + k16 * 32 + a_col_l;
                ldsm_x4(a[mt][0], a[mt][1], a[mt][2], a[mt][3], cur_sa + swz(off));
            }
            #pragma unroll
            for (int nt2 = 0; nt2 < 4; nt2++) {
                uint32_t off = (uint32_t)(wn + nt2 * 16 + b_row_l) * 128 + k16 * 32 + b_col_l;
                uint32_t r0, r1, r2, r3;
                ldsm_x4(r0, r1, r2, r3, cur_sb + swz(off));
                b[nt2 * 2 + 0][0] = r0; b[nt2 * 2 + 0][1] = r1;
                b[nt2 * 2 + 1][0] = r2; b[nt2 * 2 + 1][1] = r3;
            }
            #pragma unroll
            for (int mt = 0; mt < 4; mt++)
                #pragma unroll
                for (int nt = 0; nt < 8; nt++)
                    mma16816(acc[mt][nt], a[mt], b[nt]);
        }

        __syncthreads();
        if (kc + STAGES < NK) load_stage(kc + STAGES, s);
        s++;
        if (s == STAGES) s = 0;
    }

    const int erow = lane >> 2;
    const int ecol = (lane & 3) * 2;

    #pragma unroll
    for (int mt = 0; mt < 4; mt++) {
        #pragma unroll
        for (int h = 0; h < 2; h++) {
            const int gm = m0 + wm + mt * 16 + h * 8 + erow;
            float brow = (bias_mode == 2) ? bias[gm] : 0.f;
            #pragma unroll
            for (int nt = 0; nt < 8; nt++) {
                const int gn = n0 + wn + nt * 8 + ecol;
                float x0 = acc[mt][nt][h * 2 + 0] * alpha;
                float x1 = acc[mt][nt][h * 2 + 1] * alpha;
                if (bias_mode == 1) { x0 += bias[gn]; x1 += bias[gn + 1]; }
                else if (bias_mode == 2) { x0 += brow; x1 += brow; }
                if (Cf) {
                    float2 v; v.x = x0; v.y = x1;
                    *(float2*)(Cf + bz * batC + (size_t)gm * ldc + gn) = v;
                } else {
                    __half2 hv = __floats2half2_rn(x0, x1);
                    *(__half2*)(Ch + bz * batC + (size_t)gm * ldc + gn) = hv;
                }
            }
        }
    }
}

// ---------------- elementwise / small kernels ----------------
__global__ __launch_bounds__(256) void cast_fp16_2(
    const float* __restrict__ x0, __half* __restrict__ y0,
    const float* __restrict__ x1, __half* __restrict__ y1, int n0)
{
    const bool f = (int)blockIdx.x < n0;
    const float* x = f ? x0 : x1;
    __half* y = f ? y0 : y1;
    size_t i = ((size_t)(f ? blockIdx.x : blockIdx.x - n0) * 256 + threadIdx.x);
    float4 v = *(const float4*)(x + i * 4);
    __half2 h0 = __floats2half2_rn(v.x, v.y);
    __half2 h1 = __floats2half2_rn(v.z, v.w);
    uint2 u;
    u.x = *(uint32_t*)&h0;
    u.y = *(uint32_t*)&h1;
    *(uint2*)(y + i * 4) = u;
}

__global__ __launch_bounds__(256) void tcast2(
    const float* __restrict__ Wq, const float* __restrict__ Wk,
    __half* __restrict__ oq, __half* __restrict__ ok)
{
    __shared__ __half tile[32][33];
    const float* in = blockIdx.z ? Wk : Wq;
    __half* out = blockIdx.z ? ok : oq;
    const int bx = blockIdx.x * 32;
    const int by = blockIdx.y * 32;
    const int tx = threadIdx.x & 31;
    const int ty = threadIdx.x >> 5;
    #pragma unroll
    for (int i = 0; i < 32; i += 8)
        tile[ty + i][tx] = __float2half(in[(size_t)(by + ty + i) * C_ + bx + tx]);
    __syncthreads();
    #pragma unroll
    for (int i = 0; i < 32; i += 8)
        out[(size_t)(bx + ty + i) * C_ + by + tx] = tile[tx][ty + i];
}

__global__ __launch_bounds__(256) void wvec_p(
    const float* __restrict__ Wq, const float* __restrict__ Wk,
    const float* __restrict__ bq, const float* __restrict__ bk)
{
    const int bid = blockIdx.x;
    if (bid < 64) {
        const bool isq = bid < 32;
        const float* W = isq ? Wq : Wk;
        const float* bb = isq ? bk : bq;
        float* dst = isq ? &g_w1p[0][0] : &g_w2p[0][0];
        int lb = isq ? bid : bid - 32;
        int c = (lb & 3) * 256 + threadIdx.x;
        int dchunk = lb >> 2;
        float s = 0.f;
        #pragma unroll 4
        for (int d = dchunk * 128; d < dchunk * 128 + 128; d++)
            s += W[(size_t)d * C_ + c] * bb[d];
        dst[dchunk * C_ + c] = s;
    } else {
        const int tid = threadIdx.x;
        float s = 0.f;
        for (int d = tid; d < C_; d += 256) s += bq[d] * bk[d];
        __shared__ float red[8];
        #pragma unroll
        for (int off = 16; off > 0; off >>= 1)
            s += __shfl_xor_sync(0xffffffffu, s, off);
        if ((tid & 31) == 0) red[tid >> 5] = s;
        __syncthreads();
        if (tid == 0) {
            float t = 0.f;
            for (int w = 0; w < 8; w++) t += red[w];
            g_cc = t;
        }
    }
}

// fold partials ONCE: 8 blocks (4 for w1, 4 for w2)
__global__ __launch_bounds__(256) void wfold()
{
    const int bid = blockIdx.x;
    const bool is1 = bid < 4;
    const float* src = is1 ? &g_w1p[0][0] : &g_w2p[0][0];
    float* dst = is1 ? g_w1 : g_w2;
    int c = ((is1 ? bid : bid - 4) & 3) * 256 + threadIdx.x;
    float s = 0.f;
    #pragma unroll
    for (int p = 0; p < 8; p++) s += src[p * C_ + c];
    dst[c] = s;
}

// u32[i] = (h_i.w1 + cc)/32 ; v32[i] = (h_i.w2)/32 ; 8 rows per block, folded w
__global__ __launch_bounds__(256) void uvvec(const __half* __restrict__ hh)
{
    __shared__ float w1s[C_], w2s[C_];
    const int tid = threadIdx.x;
    for (int i = tid; i < C_; i += 256) { w1s[i] = g_w1[i]; w2s[i] = g_w2[i]; }
    __syncthreads();
    const int lane = tid & 31;
    const int warp = tid >> 5;
    const int row = blockIdx.x * 8 + warp;
    const __half2* hr = (const __half2*)(hh + (size_t)row * C_);
    float s1 = 0.f, s2 = 0.f;
    #pragma unroll
    for (int k = 0; k < 16; k++) {
        int idx = lane + k * 32;
        float2 fv = __half22float2(hr[idx]);
        s1 += fv.x * w1s[2 * idx] + fv.y * w1s[2 * idx + 1];
        s2 += fv.x * w2s[2 * idx] + fv.y * w2s[2 * idx + 1];
    }
    #pragma unroll
    for (int off = 16; off > 0; off >>= 1) {
        s1 += __shfl_xor_sync(0xffffffffu, s1, off);
        s2 += __shfl_xor_sync(0xffffffffu, s2, off);
    }
    if (lane == 0) {
        g_u32[row] = (s1 + g_cc) * (1.0f / 32.0f);
        g_v32[row] = s2 * (1.0f / 32.0f);
    }
}

__global__ __launch_bounds__(256) void softmax_h(
    float* __restrict__ P, __half* __restrict__ Ph)
{
    const size_t row = blockIdx.x;
    float* p = P + row * (size_t)N_;
    __half* ph = Ph + row * (size_t)N_;
    const float* vb = g_v32 + (row >> 11 << 11);
    const float uadd = g_u32[row];
    const int tid = threadIdx.x;
    const int lane = tid & 31;
    const int warp = tid >> 5;

    float vals[8];
    float m = -INFINITY;
    #pragma unroll
    for (int i = 0; i < 8; i++) {
        int j = tid + i * 256;
        vals[i] = p[j] + uadd + vb[j];
        m = fmaxf(m, vals[i]);
    }
    __shared__ float redmax[8], redsum[8];
    #pragma unroll
    for (int off = 16; off > 0; off >>= 1)
        m = fmaxf(m, __shfl_xor_sync(0xffffffffu, m, off));
    if (lane == 0) redmax[warp] = m;
    __syncthreads();
    float rowmax = redmax[0];
    #pragma unroll
    for (int w = 1; w < 8; w++) rowmax = fmaxf(rowmax, redmax[w]);

    float sum = 0.f;
    #pragma unroll
    for (int i = 0; i < 8; i++) {
        vals[i] = __expf(vals[i] - rowmax);
        sum += vals[i];
    }
    #pragma unroll
    for (int off = 16; off > 0; off >>= 1)
        sum += __shfl_xor_sync(0xffffffffu, sum, off);
    if (lane == 0) redsum[warp] = sum;
    __syncthreads();
    float total = 0.f;
    #pragma unroll
    for (int w = 0; w < 8; w++) total += redsum[w];
    float inv = 1.f / total;

    #pragma unroll
    for (int i = 0; i < 8; i++) {
        float v = vals[i] * inv;
        p[tid + i * 256] = v;
        ph[tid + i * 256] = __float2half(v);
    }
}

// ---------------- launch ----------------
extern "C" void kernel_launch(void* const* d_in, const int* in_sizes, int n_in,
                              void* d_out, int out_size)
{
    const float* h  = (const float*)d_in[0];
    const float* Wq = (const float*)d_in[1];
    const float* bq = (const float*)d_in[2];
    const float* Wk = (const float*)d_in[3];
    const float* bk = (const float*)d_in[4];
    const float* Wv = (const float*)d_in[5];
    const float* bv = (const float*)d_in[6];

    float* out  = (float*)d_out;
    float* attn = out + (size_t)B_ * N_ * C_;

    __half *hh, *Wvh, *WqT, *WkT, *MT, *QM, *VT, *P;
    cudaGetSymbolAddress((void**)&hh,  g_hh);
    cudaGetSymbolAddress((void**)&Wvh, g_Wvh);
    cudaGetSymbolAddress((void**)&WqT, g_WqT);
    cudaGetSymbolAddress((void**)&WkT, g_WkT);
    cudaGetSymbolAddress((void**)&MT,  g_MT);
    cudaGetSymbolAddress((void**)&QM,  g_QM);
    cudaGetSymbolAddress((void**)&VT,  g_VT);
    cudaGetSymbolAddress((void**)&P,   g_P);

    cudaFuncSetAttribute(gemm_seg, cudaFuncAttributeMaxDynamicSharedMemorySize, SMEM_GEMM);

    // 1) casts / transposes / bias partials + fold
    {
        int nh = (int)((size_t)M_TOT * C_ / 4 / 256);
        int nw = (int)((size_t)C_ * C_ / 4 / 256);
        cast_fp16_2<<<nh + nw, 256>>>(h, hh, Wv, Wvh, nh);
        dim3 tg(C_ / 32, C_ / 32, 2);
        tcast2<<<tg, 256>>>(Wq, Wk, WqT, WkT);
        wvec_p<<<65, 256>>>(Wq, Wk, bq, bk);
        wfold<<<8, 256>>>();
        uvvec<<<M_TOT / 8, 256>>>(hh);
    }

    auto mkseg = [](const __half* A, const __half* B, long long bA, long long bB,
                    long long bC, int lda, int ldb, int ldc, int K,
                    float* Cf, __half* Ch, float alpha,
                    const float* bias, int bias_mode, int gx, int gy) {
        GemmSeg s;
        s.A = A; s.B = B; s.batA = bA; s.batB = bB; s.batC = bC;
        s.lda = lda; s.ldb = ldb; s.ldc = ldc; s.K = K;
        s.Cf = Cf; s.Ch = Ch; s.alpha = alpha; s.bias = bias; s.bias_mode = bias_mode;
        s.gx = gx; s.gxy = gx * gy;
        return s;
    };

    // 2) merged: VT = Wvh @ hh^T + bv (row bias) [256] ; MT = WkT @ WqT^T [32]
    {
        GemmSeg sVT = mkseg(Wvh, hh, 0, 0, 0, C_, C_, M_TOT, C_,
                            nullptr, VT, 1.0f, bv, 2, M_TOT / BN_, C_ / BM_);
        GemmSeg sMT = mkseg(WkT, WqT, 0, 0, 0, C_, C_, C_, C_,
                            nullptr, MT, 1.0f, nullptr, 0, C_ / BN_, C_ / BM_);
        int n0 = (M_TOT / BN_) * (C_ / BM_);
        int n1 = (C_ / BN_) * (C_ / BM_);
        gemm_seg<<<n0 + n1, 256, SMEM_GEMM>>>(sVT, sMT, n0);
    }
    // 3) QM = hh @ MT^T  [256 CTAs]
    {
        GemmSeg s = mkseg(hh, MT, 0, 0, 0, C_, C_, C_, C_,
                          nullptr, QM, 1.0f, nullptr, 0, C_ / BN_, M_TOT / BM_);
        gemm_seg<<<s.gxy, 256, SMEM_GEMM>>>(s, s, s.gxy);
    }
    // 4) scores = (QM_b @ hh_b^T)/32 -> fp32 attn  [512 CTAs]
    {
        GemmSeg s = mkseg(QM, hh, (long long)N_ * C_, (long long)N_ * C_,
                          (long long)N_ * N_, C_, C_, N_, C_,
                          attn, nullptr, 1.0f / 32.0f, nullptr, 0, N_ / BN_, N_ / BM_);
        int n = s.gxy * B_;
        gemm_seg<<<n, 256, SMEM_GEMM>>>(s, s, n);
    }
    // 5) softmax + fp16 P
    softmax_h<<<B_ * N_, 256>>>(attn, P);

    // 6) out = P_b @ VT_b^T  [256 CTAs]
    {
        GemmSeg s = mkseg(P, VT, (long long)N_ * N_, (long long)N_,
                          (long long)N_ * C_, N_, M_TOT, C_, N_,
                          out, nullptr, 1.0f, nullptr, 0, C_ / BN_, N_ / BM_);
        int n = s.gxy * B_;
        gemm_seg<<<n, 256, SMEM_GEMM>>>(s, s, n);
    }
}

// round 14
// speedup vs baseline: 1.0913x; 1.0821x over previous
#include <cuda_runtime.h>
#include <cuda_fp16.h>
#include <math.h>
#include <stdint.h>

#define B_ 4
#define N_ 2048
#define C_ 1024
#define M_TOT (B_ * N_)   // 8192

// ---------------- scratch (__device__ globals; no allocation) ----------------
__device__ __align__(128) __half g_hh[(size_t)M_TOT * C_];
__device__ __align__(128) __half g_Wvh[C_ * C_];
__device__ __align__(128) __half g_WqT[C_ * C_];
__device__ __align__(128) __half g_WkT[C_ * C_];
__device__ __align__(128) __half g_MT[C_ * C_];
__device__ __align__(128) __half g_QM[(size_t)M_TOT * C_];
__device__ __align__(128) __half g_VT[(size_t)C_ * M_TOT];
__device__ __align__(128) __half g_P[(size_t)B_ * N_ * N_];
__device__ float g_w1p[8][C_], g_w2p[8][C_];
__device__ float g_w1[C_], g_w2[C_];
__device__ float g_u32[M_TOT], g_v32[M_TOT];
__device__ float g_cc;
// flags: [0]=MT done count (32), [1..64]=QM per-m-tile counts (4 each), [65]=wfold (8)
__device__ int g_flags[80];

// ---------------- portable PTX helpers ----------------
__device__ __forceinline__ uint32_t smem_u32(const void* p) {
    uint32_t a;
    asm("{ .reg .u64 t; cvta.to.shared.u64 t, %1; cvt.u32.u64 %0, t; }" : "=r"(a) : "l"(p));
    return a;
}
__device__ __forceinline__ void cp_async16(uint32_t dst, const void* src) {
    asm volatile("cp.async.cg.shared.global [%0], [%1], 16;" :: "r"(dst), "l"(src) : "memory");
}
#define CP_COMMIT()  asm volatile("cp.async.commit_group;" ::: "memory")
#define CP_WAIT(n)   asm volatile("cp.async.wait_group %0;" :: "n"(n) : "memory")

__device__ __forceinline__ void ldsm_x4(uint32_t& r0, uint32_t& r1, uint32_t& r2, uint32_t& r3,
                                        uint32_t addr) {
    asm volatile("ldmatrix.sync.aligned.m8n8.x4.shared.b16 {%0,%1,%2,%3}, [%4];"
                 : "=r"(r0), "=r"(r1), "=r"(r2), "=r"(r3) : "r"(addr));
}
__device__ __forceinline__ void mma16816(float* d, const uint32_t* a, const uint32_t* b) {
    asm volatile(
        "mma.sync.aligned.m16n8k16.row.col.f32.f16.f16.f32 "
        "{%0,%1,%2,%3}, {%4,%5,%6,%7}, {%8,%9}, {%0,%1,%2,%3};"
        : "+f"(d[0]), "+f"(d[1]), "+f"(d[2]), "+f"(d[3])
        : "r"(a[0]), "r"(a[1]), "r"(a[2]), "r"(a[3]), "r"(b[0]), "r"(b[1]));
}
__device__ __forceinline__ uint32_t swz(uint32_t off) { return off ^ ((off >> 3) & 0x70); }

__device__ __forceinline__ int ld_acq(const int* p) {
    int v;
    asm volatile("ld.acquire.gpu.global.s32 %0, [%1];" : "=r"(v) : "l"(p));
    return v;
}
__device__ __forceinline__ void spin_ge(const int* p, int target) {
    while (ld_acq(p) < target) { __nanosleep(64); }
}

// ---------------- segmented fp16 GEMM (4 segments + flag deps) ----------------
// Block tile 128x256, BK=64; 8 warps 2(m)x4(n), warp tile 64x64.
#define BM_ 128
#define BN_ 256
#define STAGES 3
#define TILE_A_BYTES 16384
#define STAGE_BYTES  49152
#define SMEM_GEMM (STAGES * STAGE_BYTES)   // 144 KB

struct GemmSeg {
    const __half* A; const __half* B;
    long long batA, batB, batC;
    int lda, ldb, ldc, K;
    float* Cf; __half* Ch;
    float alpha;
    const float* bias; int bias_mode;
    int gx, gxy;
    // flag protocol
    int wmode;    // 0 none; 1 wait flags[widx] >= wtarget; 2 wait flags[widx + mtile] >= wtarget
    int widx, wtarget;
    int smode;    // 0 none; 1 flags[sidx] += 1; 2 flags[sidx + mtile] += 1
    int sidx;
};

__global__ __launch_bounds__(256, 1) void gemm_seg4(
    GemmSeg s0, GemmSeg s1, GemmSeg s2, GemmSeg s3, int e0, int e1, int e2)
{
    extern __shared__ char smem[];
    const uint32_t sbase = smem_u32(smem);
    const int tid  = threadIdx.x;
    const int wid  = tid >> 5;
    const int lane = tid & 31;

    GemmSeg S;
    int lid;
    {
        const int bi = (int)blockIdx.x;
        if (bi < e0)      { S = s0; lid = bi; }
        else if (bi < e1) { S = s1; lid = bi - e0; }
        else if (bi < e2) { S = s2; lid = bi - e1; }
        else              { S = s3; lid = bi - e2; }
    }

    const long long bz = lid / S.gxy;
    int r = lid - (int)bz * S.gxy;
    const int m0 = (r / S.gx) * BM_;
    const int n0 = (r % S.gx) * BN_;
    const int gy = S.gxy / S.gx;
    const int mtile = (int)bz * gy + m0 / BM_;

    // dependency wait (before any loads)
    if (S.wmode) {
        int idx = S.widx + (S.wmode == 2 ? mtile : 0);
        if (tid == 0) spin_ge(&g_flags[idx], S.wtarget);
        __syncthreads();
    }

    const __half* Ap = S.A + bz * S.batA;
    const __half* Bp = S.B + bz * S.batB;

    const int wm = (wid >> 2) * 64;
    const int wn = (wid & 3) * 64;

    const int NK = S.K >> 6;
    const int lda = S.lda, ldb = S.ldb;

    const int lrow = tid >> 3;
    const int lch  = tid & 7;

    auto load_stage = [&](int kc, int s) {
        const __half* Asrc = Ap + (size_t)m0 * lda + kc * 64;
        const __half* Bsrc = Bp + (size_t)n0 * ldb + kc * 64;
        const uint32_t sa = sbase + s * STAGE_BYTES;
        const uint32_t sb = sa + TILE_A_BYTES;
        #pragma unroll
        for (int rr = 0; rr < 4; rr++) {
            int row = rr * 32 + lrow;
            uint32_t sw = swz(row * 128 + lch * 16);
            cp_async16(sa + sw, Asrc + (size_t)row * lda + lch * 8);
        }
        #pragma unroll
        for (int rr = 0; rr < 8; rr++) {
            int row = rr * 32 + lrow;
            uint32_t sw = swz(row * 128 + lch * 16);
            cp_async16(sb + sw, Bsrc + (size_t)row * ldb + lch * 8);
        }
        CP_COMMIT();
    };

    float acc[4][8][4];
    #pragma unroll
    for (int i = 0; i < 4; i++)
        #pragma unroll
        for (int j = 0; j < 8; j++)
            #pragma unroll
            for (int e = 0; e < 4; e++) acc[i][j][e] = 0.f;

    const int a_row_l = ((lane >> 3) & 1) * 8 + (lane & 7);
    const int a_col_l = ((lane >> 4) & 1) * 16;
    const int b_row_l = ((lane >> 4) & 1) * 8 + (lane & 7);
    const int b_col_l = ((lane >> 3) & 1) * 16;

    #pragma unroll
    for (int i = 0; i < STAGES; i++)
        if (i < NK) load_stage(i, i);

    int s = 0;
    for (int kc = 0; kc < NK; kc++) {
        int rem = NK - 1 - kc;
        if (rem >= 2)      { CP_WAIT(2); }
        else if (rem == 1) { CP_WAIT(1); }
        else               { CP_WAIT(0); }
        __syncthreads();

        const uint32_t cur_sa = sbase + s * STAGE_BYTES;
        const uint32_t cur_sb = cur_sa + TILE_A_BYTES;

        #pragma unroll
        for (int k16 = 0; k16 < 4; k16++) {
            uint32_t a[4][4], b[8][2];
            #pragma unroll
            for (int mt = 0; mt < 4; mt++) {
                uint32_t off = (uint32_t)(wm + mt * 16 + a_row_l) * 128 + k16 * 32 + a_col_l;
                ldsm_x4(a[mt][0], a[mt][1], a[mt][2], a[mt][3], cur_sa + swz(off));
            }
            #pragma unroll
            for (int nt2 = 0; nt2 < 4; nt2++) {
                uint32_t off = (uint32_t)(wn + nt2 * 16 + b_row_l) * 128 + k16 * 32 + b_col_l;
                uint32_t r0, r1, r2, r3;
                ldsm_x4(r0, r1, r2, r3, cur_sb + swz(off));
                b[nt2 * 2 + 0][0] = r0; b[nt2 * 2 + 0][1] = r1;
                b[nt2 * 2 + 1][0] = r2; b[nt2 * 2 + 1][1] = r3;
            }
            #pragma unroll
            for (int mt = 0; mt < 4; mt++)
                #pragma unroll
                for (int nt = 0; nt < 8; nt++)
                    mma16816(acc[mt][nt], a[mt], b[nt]);
        }

        __syncthreads();
        if (kc + STAGES < NK) load_stage(kc + STAGES, s);
        s++;
        if (s == STAGES) s = 0;
    }

    // epilogue
    const int erow = lane >> 2;
    const int ecol = (lane & 3) * 2;

    #pragma unroll
    for (int mt = 0; mt < 4; mt++) {
        #pragma unroll
        for (int h = 0; h < 2; h++) {
            const int gm = m0 + wm + mt * 16 + h * 8 + erow;
            float brow = (S.bias_mode == 2) ? S.bias[gm] : 0.f;
            #pragma unroll
            for (int nt = 0; nt < 8; nt++) {
                const int gn = n0 + wn + nt * 8 + ecol;
                float x0 = acc[mt][nt][h * 2 + 0] * S.alpha;
                float x1 = acc[mt][nt][h * 2 + 1] * S.alpha;
                if (S.bias_mode == 1) { x0 += S.bias[gn]; x1 += S.bias[gn + 1]; }
                else if (S.bias_mode == 2) { x0 += brow; x1 += brow; }
                if (S.Cf) {
                    float2 v; v.x = x0; v.y = x1;
                    *(float2*)(S.Cf + bz * S.batC + (size_t)gm * S.ldc + gn) = v;
                } else {
                    __half2 hv = __floats2half2_rn(x0, x1);
                    *(__half2*)(S.Ch + bz * S.batC + (size_t)gm * S.ldc + gn) = hv;
                }
            }
        }
    }

    // completion signal
    if (S.smode) {
        __threadfence();
        __syncthreads();
        if (tid == 0) {
            int idx = S.sidx + (S.smode == 2 ? mtile : 0);
            atomicAdd(&g_flags[idx], 1);
        }
    }
}

// ---------------- elementwise / small kernels ----------------
__global__ void zeroflags()
{
    if (threadIdx.x < 80) g_flags[threadIdx.x] = 0;
}

__global__ __launch_bounds__(256) void cast_fp16_2(
    const float* __restrict__ x0, __half* __restrict__ y0,
    const float* __restrict__ x1, __half* __restrict__ y1, int n0)
{
    const bool f = (int)blockIdx.x < n0;
    const float* x = f ? x0 : x1;
    __half* y = f ? y0 : y1;
    size_t i = ((size_t)(f ? blockIdx.x : blockIdx.x - n0) * 256 + threadIdx.x);
    float4 v = *(const float4*)(x + i * 4);
    __half2 h0 = __floats2half2_rn(v.x, v.y);
    __half2 h1 = __floats2half2_rn(v.z, v.w);
    uint2 u;
    u.x = *(uint32_t*)&h0;
    u.y = *(uint32_t*)&h1;
    *(uint2*)(y + i * 4) = u;
}

__global__ __launch_bounds__(256) void tcast2(
    const float* __restrict__ Wq, const float* __restrict__ Wk,
    __half* __restrict__ oq, __half* __restrict__ ok)
{
    __shared__ __half tile[32][33];
    const float* in = blockIdx.z ? Wk : Wq;
    __half* out = blockIdx.z ? ok : oq;
    const int bx = blockIdx.x * 32;
    const int by = blockIdx.y * 32;
    const int tx = threadIdx.x & 31;
    const int ty = threadIdx.x >> 5;
    #pragma unroll
    for (int i = 0; i < 32; i += 8)
        tile[ty + i][tx] = __float2half(in[(size_t)(by + ty + i) * C_ + bx + tx]);
    __syncthreads();
    #pragma unroll
    for (int i = 0; i < 32; i += 8)
        out[(size_t)(bx + ty + i) * C_ + by + tx] = tile[tx][ty + i];
}

__global__ __launch_bounds__(256) void wvec_p(
    const float* __restrict__ Wq, const float* __restrict__ Wk,
    const float* __restrict__ bq, const float* __restrict__ bk)
{
    const int bid = blockIdx.x;
    if (bid < 64) {
        const bool isq = bid < 32;
        const float* W = isq ? Wq : Wk;
        const float* bb = isq ? bk : bq;
        float* dst = isq ? &g_w1p[0][0] : &g_w2p[0][0];
        int lb = isq ? bid : bid - 32;
        int c = (lb & 3) * 256 + threadIdx.x;
        int dchunk = lb >> 2;
        float s = 0.f;
        #pragma unroll 4
        for (int d = dchunk * 128; d < dchunk * 128 + 128; d++)
            s += W[(size_t)d * C_ + c] * bb[d];
        dst[dchunk * C_ + c] = s;
    } else {
        const int tid = threadIdx.x;
        float s = 0.f;
        for (int d = tid; d < C_; d += 256) s += bq[d] * bk[d];
        __shared__ float red[8];
        #pragma unroll
        for (int off = 16; off > 0; off >>= 1)
            s += __shfl_xor_sync(0xffffffffu, s, off);
        if ((tid & 31) == 0) red[tid >> 5] = s;
        __syncthreads();
        if (tid == 0) {
            float t = 0.f;
            for (int w = 0; w < 8; w++) t += red[w];
            g_cc = t;
        }
    }
}

// uvvec with integrated fold: blocks 0..7 fold partials -> g_w1/g_w2, signal flag 65;
// all blocks wait flag 65 >= 8, then compute u/v for 8 rows each.
__global__ __launch_bounds__(256) void uvvec(const __half* __restrict__ hh)
{
    const int tid = threadIdx.x;
    if (blockIdx.x < 8) {
        const bool is1 = blockIdx.x < 4;
        const float* src = is1 ? &g_w1p[0][0] : &g_w2p[0][0];
        float* dst = is1 ? g_w1 : g_w2;
        int c = ((int)(is1 ? blockIdx.x : blockIdx.x - 4) & 3) * 256 + tid;
        float sum = 0.f;
        #pragma unroll
        for (int p = 0; p < 8; p++) sum += src[p * C_ + c];
        dst[c] = sum;
        __threadfence();
        __syncthreads();
        if (tid == 0) atomicAdd(&g_flags[65], 1);
    }
    if (tid == 0) spin_ge(&g_flags[65], 8);
    __syncthreads();

    __shared__ float w1s[C_], w2s[C_];
    for (int i = tid; i < C_; i += 256) { w1s[i] = g_w1[i]; w2s[i] = g_w2[i]; }
    __syncthreads();
    const int lane = tid & 31;
    const int warp = tid >> 5;
    const int row = blockIdx.x * 8 + warp;
    const __half2* hr = (const __half2*)(hh + (size_t)row * C_);
    float s1 = 0.f, s2 = 0.f;
    #pragma unroll
    for (int k = 0; k < 16; k++) {
        int idx = lane + k * 32;
        float2 fv = __half22float2(hr[idx]);
        s1 += fv.x * w1s[2 * idx] + fv.y * w1s[2 * idx + 1];
        s2 += fv.x * w2s[2 * idx] + fv.y * w2s[2 * idx + 1];
    }
    #pragma unroll
    for (int off = 16; off > 0; off >>= 1) {
        s1 += __shfl_xor_sync(0xffffffffu, s1, off);
        s2 += __shfl_xor_sync(0xffffffffu, s2, off);
    }
    if (lane == 0) {
        g_u32[row] = (s1 + g_cc) * (1.0f / 32.0f);
        g_v32[row] = s2 * (1.0f / 32.0f);
    }
}

__global__ __launch_bounds__(256) void softmax_h(
    float* __restrict__ P, __half* __restrict__ Ph)
{
    const size_t row = blockIdx.x;
    float* p = P + row * (size_t)N_;
    __half* ph = Ph + row * (size_t)N_;
    const float* vb = g_v32 + (row >> 11 << 11);
    const float uadd = g_u32[row];
    const int tid = threadIdx.x;
    const int lane = tid & 31;
    const int warp = tid >> 5;

    float vals[8];
    float m = -INFINITY;
    #pragma unroll
    for (int i = 0; i < 8; i++) {
        int j = tid + i * 256;
        vals[i] = p[j] + uadd + vb[j];
        m = fmaxf(m, vals[i]);
    }
    __shared__ float redmax[8], redsum[8];
    #pragma unroll
    for (int off = 16; off > 0; off >>= 1)
        m = fmaxf(m, __shfl_xor_sync(0xffffffffu, m, off));
    if (lane == 0) redmax[warp] = m;
    __syncthreads();
    float rowmax = redmax[0];
    #pragma unroll
    for (int w = 1; w < 8; w++) rowmax = fmaxf(rowmax, redmax[w]);

    float sum = 0.f;
    #pragma unroll
    for (int i = 0; i < 8; i++) {
        vals[i] = __expf(vals[i] - rowmax);
        sum += vals[i];
    }
    #pragma unroll
    for (int off = 16; off > 0; off >>= 1)
        sum += __shfl_xor_sync(0xffffffffu, sum, off);
    if (lane == 0) redsum[warp] = sum;
    __syncthreads();
    float total = 0.f;
    #pragma unroll
    for (int w = 0; w < 8; w++) total += redsum[w];
    float inv = 1.f / total;

    #pragma unroll
    for (int i = 0; i < 8; i++) {
        float v = vals[i] * inv;
        p[tid + i * 256] = v;
        ph[tid + i * 256] = __float2half(v);
    }
}

// ---------------- launch ----------------
extern "C" void kernel_launch(void* const* d_in, const int* in_sizes, int n_in,
                              void* d_out, int out_size)
{
    const float* h  = (const float*)d_in[0];
    const float* Wq = (const float*)d_in[1];
    const float* bq = (const float*)d_in[2];
    const float* Wk = (const float*)d_in[3];
    const float* bk = (const float*)d_in[4];
    const float* Wv = (const float*)d_in[5];
    const float* bv = (const float*)d_in[6];

    float* out  = (float*)d_out;
    float* attn = out + (size_t)B_ * N_ * C_;

    __half *hh, *Wvh, *WqT, *WkT, *MT, *QM, *VT, *P;
    cudaGetSymbolAddress((void**)&hh,  g_hh);
    cudaGetSymbolAddress((void**)&Wvh, g_Wvh);
    cudaGetSymbolAddress((void**)&WqT, g_WqT);
    cudaGetSymbolAddress((void**)&WkT, g_WkT);
    cudaGetSymbolAddress((void**)&MT,  g_MT);
    cudaGetSymbolAddress((void**)&QM,  g_QM);
    cudaGetSymbolAddress((void**)&VT,  g_VT);
    cudaGetSymbolAddress((void**)&P,   g_P);

    cudaFuncSetAttribute(gemm_seg4, cudaFuncAttributeMaxDynamicSharedMemorySize, SMEM_GEMM);

    // 0) reset flags (graph-replay safe)
    zeroflags<<<1, 128>>>();

    // 1) casts / transposes / bias partials (+fold inside uvvec)
    {
        int nh = (int)((size_t)M_TOT * C_ / 4 / 256);
        int nw = (int)((size_t)C_ * C_ / 4 / 256);
        cast_fp16_2<<<nh + nw, 256>>>(h, hh, Wv, Wvh, nh);
        dim3 tg(C_ / 32, C_ / 32, 2);
        tcast2<<<tg, 256>>>(Wq, Wk, WqT, WkT);
        wvec_p<<<65, 256>>>(Wq, Wk, bq, bk);
        uvvec<<<M_TOT / 8, 256>>>(hh);
    }

    auto mkseg = [](const __half* A, const __half* B, long long bA, long long bB,
                    long long bC, int lda, int ldb, int ldc, int K,
                    float* Cf, __half* Ch, float alpha,
                    const float* bias, int bias_mode, int gx, int gy,
                    int wmode, int widx, int wtarget, int smode, int sidx) {
        GemmSeg s;
        s.A = A; s.B = B; s.batA = bA; s.batB = bB; s.batC = bC;
        s.lda = lda; s.ldb = ldb; s.ldc = ldc; s.K = K;
        s.Cf = Cf; s.Ch = Ch; s.alpha = alpha; s.bias = bias; s.bias_mode = bias_mode;
        s.gx = gx; s.gxy = gx * gy;
        s.wmode = wmode; s.widx = widx; s.wtarget = wtarget;
        s.smode = smode; s.sidx = sidx;
        return s;
    };

    // 2) MEGA launch: MT(32) -> signals flags[0]; VT(256); QM(256) waits flags[0]>=32,
    //    signals flags[1+mtile]; scores(512) waits flags[1+mtile]>=4.
    {
        GemmSeg sMT = mkseg(WkT, WqT, 0, 0, 0, C_, C_, C_, C_,
                            nullptr, MT, 1.0f, nullptr, 0, C_ / BN_, C_ / BM_,
                            0, 0, 0, 1, 0);
        GemmSeg sVT = mkseg(Wvh, hh, 0, 0, 0, C_, C_, M_TOT, C_,
                            nullptr, VT, 1.0f, bv, 2, M_TOT / BN_, C_ / BM_,
                            0, 0, 0, 0, 0);
        GemmSeg sQM = mkseg(hh, MT, 0, 0, 0, C_, C_, C_, C_,
                            nullptr, QM, 1.0f, nullptr, 0, C_ / BN_, M_TOT / BM_,
                            1, 0, 32, 2, 1);
        GemmSeg sSC = mkseg(QM, hh, (long long)N_ * C_, (long long)N_ * C_,
                            (long long)N_ * N_, C_, C_, N_, C_,
                            attn, nullptr, 1.0f / 32.0f, nullptr, 0, N_ / BN_, N_ / BM_,
                            2, 1, 4, 0, 0);
        int nMT = 32, nVT = 256, nQM = 256, nSC = 512;
        int e0 = nMT, e1 = e0 + nVT, e2 = e1 + nQM;
        gemm_seg4<<<e2 + nSC, 256, SMEM_GEMM>>>(sMT, sVT, sQM, sSC, e0, e1, e2);
    }
    // 3) softmax + fp16 P
    softmax_h<<<B_ * N_, 256>>>(attn, P);

    // 4) out = P_b @ VT_b^T  [256 CTAs]
    {
        GemmSeg s = mkseg(P, VT, (long long)N_ * N_, (long long)N_,
                          (long long)N_ * C_, N_, M_TOT, C_, N_,
                          out, nullptr, 1.0f, nullptr, 0, C_ / BN_, N_ / BM_,
                          0, 0, 0, 0, 0);
        int n = s.gxy * B_;
        gemm_seg4<<<n, 256, SMEM_GEMM>>>(s, s, s, s, n, n, n);
    }
}

// round 15
// speedup vs baseline: 1.1337x; 1.0389x over previous
#include <cuda_runtime.h>
#include <cuda_fp16.h>
#include <math.h>
#include <stdint.h>

#define B_ 4
#define N_ 2048
#define C_ 1024
#define M_TOT (B_ * N_)   // 8192

// ---------------- scratch (__device__ globals; no allocation) ----------------
__device__ __align__(128) __half g_hh[(size_t)M_TOT * C_];
__device__ __align__(128) __half g_Wvh[C_ * C_];
__device__ __align__(128) __half g_WqT[C_ * C_];
__device__ __align__(128) __half g_WkT[C_ * C_];
__device__ __align__(128) __half g_MT[C_ * C_];
__device__ __align__(128) __half g_QM[(size_t)M_TOT * C_];
__device__ __align__(128) __half g_VT[(size_t)C_ * M_TOT];
__device__ __align__(128) __half g_P[(size_t)B_ * N_ * N_];
__device__ float g_w1p[32][C_], g_w2p[32][C_];
__device__ float g_w1[C_], g_w2[C_];
__device__ float g_u32[M_TOT], g_v32[M_TOT];
__device__ float g_cc;
// flags: [0]=MT done (32); [1..64]=QM per-m-tile (4 each); [65]=fold (8);
//        [66]=h-cast blocks (8192); [67]=wvec partial blocks (257)
__device__ int g_flags[80];

// ---------------- portable PTX helpers ----------------
__device__ __forceinline__ uint32_t smem_u32(const void* p) {
    uint32_t a;
    asm("{ .reg .u64 t; cvta.to.shared.u64 t, %1; cvt.u32.u64 %0, t; }" : "=r"(a) : "l"(p));
    return a;
}
__device__ __forceinline__ void cp_async16(uint32_t dst, const void* src) {
    asm volatile("cp.async.cg.shared.global [%0], [%1], 16;" :: "r"(dst), "l"(src) : "memory");
}
#define CP_COMMIT()  asm volatile("cp.async.commit_group;" ::: "memory")
#define CP_WAIT(n)   asm volatile("cp.async.wait_group %0;" :: "n"(n) : "memory")

__device__ __forceinline__ void ldsm_x4(uint32_t& r0, uint32_t& r1, uint32_t& r2, uint32_t& r3,
                                        uint32_t addr) {
    asm volatile("ldmatrix.sync.aligned.m8n8.x4.shared.b16 {%0,%1,%2,%3}, [%4];"
                 : "=r"(r0), "=r"(r1), "=r"(r2), "=r"(r3) : "r"(addr));
}
__device__ __forceinline__ void mma16816(float* d, const uint32_t* a, const uint32_t* b) {
    asm volatile(
        "mma.sync.aligned.m16n8k16.row.col.f32.f16.f16.f32 "
        "{%0,%1,%2,%3}, {%4,%5,%6,%7}, {%8,%9}, {%0,%1,%2,%3};"
        : "+f"(d[0]), "+f"(d[1]), "+f"(d[2]), "+f"(d[3])
        : "r"(a[0]), "r"(a[1]), "r"(a[2]), "r"(a[3]), "r"(b[0]), "r"(b[1]));
}
__device__ __forceinline__ uint32_t swz(uint32_t off) { return off ^ ((off >> 3) & 0x70); }

__device__ __forceinline__ int ld_acq(const int* p) {
    int v;
    asm volatile("ld.acquire.gpu.global.s32 %0, [%1];" : "=r"(v) : "l"(p));
    return v;
}
__device__ __forceinline__ void spin_ge(const int* p, int target) {
    while (ld_acq(p) < target) { __nanosleep(64); }
}

// ---------------- segmented fp16 GEMM (4 segments + flag deps) ----------------
#define BM_ 128
#define BN_ 256
#define STAGES 3
#define TILE_A_BYTES 16384
#define STAGE_BYTES  49152
#define SMEM_GEMM (STAGES * STAGE_BYTES)   // 144 KB

struct GemmSeg {
    const __half* A; const __half* B;
    long long batA, batB, batC;
    int lda, ldb, ldc, K;
    float* Cf; __half* Ch;
    float alpha;
    const float* bias; int bias_mode;
    int gx, gxy;
    int wmode, widx, wtarget;   // wait protocol
    int smode, sidx;            // signal protocol
    int zflag;                  // block 0 zeroes g_flags at start (last launch only)
};

__global__ __launch_bounds__(256, 1) void gemm_seg4(
    GemmSeg s0, GemmSeg s1, GemmSeg s2, GemmSeg s3, int e0, int e1, int e2)
{
    extern __shared__ char smem[];
    const uint32_t sbase = smem_u32(smem);
    const int tid  = threadIdx.x;
    const int wid  = tid >> 5;
    const int lane = tid & 31;

    GemmSeg S;
    int lid;
    {
        const int bi = (int)blockIdx.x;
        if (bi < e0)      { S = s0; lid = bi; }
        else if (bi < e1) { S = s1; lid = bi - e0; }
        else if (bi < e2) { S = s2; lid = bi - e1; }
        else              { S = s3; lid = bi - e2; }
    }

    if (S.zflag && lid == 0 && tid < 80) g_flags[tid] = 0;

    const long long bz = lid / S.gxy;
    int r = lid - (int)bz * S.gxy;
    const int m0 = (r / S.gx) * BM_;
    const int n0 = (r % S.gx) * BN_;
    const int gy = S.gxy / S.gx;
    const int mtile = (int)bz * gy + m0 / BM_;

    if (S.wmode) {
        int idx = S.widx + (S.wmode == 2 ? mtile : 0);
        if (tid == 0) spin_ge(&g_flags[idx], S.wtarget);
        __syncthreads();
    }

    const __half* Ap = S.A + bz * S.batA;
    const __half* Bp = S.B + bz * S.batB;

    const int wm = (wid >> 2) * 64;
    const int wn = (wid & 3) * 64;

    const int NK = S.K >> 6;
    const int lda = S.lda, ldb = S.ldb;

    const int lrow = tid >> 3;
    const int lch  = tid & 7;

    auto load_stage = [&](int kc, int s) {
        const __half* Asrc = Ap + (size_t)m0 * lda + kc * 64;
        const __half* Bsrc = Bp + (size_t)n0 * ldb + kc * 64;
        const uint32_t sa = sbase + s * STAGE_BYTES;
        const uint32_t sb = sa + TILE_A_BYTES;
        #pragma unroll
        for (int rr = 0; rr < 4; rr++) {
            int row = rr * 32 + lrow;
            uint32_t sw = swz(row * 128 + lch * 16);
            cp_async16(sa + sw, Asrc + (size_t)row * lda + lch * 8);
        }
        #pragma unroll
        for (int rr = 0; rr < 8; rr++) {
            int row = rr * 32 + lrow;
            uint32_t sw = swz(row * 128 + lch * 16);
            cp_async16(sb + sw, Bsrc + (size_t)row * ldb + lch * 8);
        }
        CP_COMMIT();
    };

    float acc[4][8][4];
    #pragma unroll
    for (int i = 0; i < 4; i++)
        #pragma unroll
        for (int j = 0; j < 8; j++)
            #pragma unroll
            for (int e = 0; e < 4; e++) acc[i][j][e] = 0.f;

    const int a_row_l = ((lane >> 3) & 1) * 8 + (lane & 7);
    const int a_col_l = ((lane >> 4) & 1) * 16;
    const int b_row_l = ((lane >> 4) & 1) * 8 + (lane & 7);
    const int b_col_l = ((lane >> 3) & 1) * 16;

    #pragma unroll
    for (int i = 0; i < STAGES; i++)
        if (i < NK) load_stage(i, i);

    int s = 0;
    for (int kc = 0; kc < NK; kc++) {
        int rem = NK - 1 - kc;
        if (rem >= 2)      { CP_WAIT(2); }
        else if (rem == 1) { CP_WAIT(1); }
        else               { CP_WAIT(0); }
        __syncthreads();

        const uint32_t cur_sa = sbase + s * STAGE_BYTES;
        const uint32_t cur_sb = cur_sa + TILE_A_BYTES;

        #pragma unroll
        for (int k16 = 0; k16 < 4; k16++) {
            uint32_t a[4][4], b[8][2];
            #pragma unroll
            for (int mt = 0; mt < 4; mt++) {
                uint32_t off = (uint32_t)(wm + mt * 16 + a_row_l) * 128 + k16 * 32 + a_col_l;
                ldsm_x4(a[mt][0], a[mt][1], a[mt][2], a[mt][3], cur_sa + swz(off));
            }
            #pragma unroll
            for (int nt2 = 0; nt2 < 4; nt2++) {
                uint32_t off = (uint32_t)(wn + nt2 * 16 + b_row_l) * 128 + k16 * 32 + b_col_l;
                uint32_t r0, r1, r2, r3;
                ldsm_x4(r0, r1, r2, r3, cur_sb + swz(off));
                b[nt2 * 2 + 0][0] = r0; b[nt2 * 2 + 0][1] = r1;
                b[nt2 * 2 + 1][0] = r2; b[nt2 * 2 + 1][1] = r3;
            }
            #pragma unroll
            for (int mt = 0; mt < 4; mt++)
                #pragma unroll
                for (int nt = 0; nt < 8; nt++)
                    mma16816(acc[mt][nt], a[mt], b[nt]);
        }

        __syncthreads();
        if (kc + STAGES < NK) load_stage(kc + STAGES, s);
        s++;
        if (s == STAGES) s = 0;
    }

    const int erow = lane >> 2;
    const int ecol = (lane & 3) * 2;

    #pragma unroll
    for (int mt = 0; mt < 4; mt++) {
        #pragma unroll
        for (int h = 0; h < 2; h++) {
            const int gm = m0 + wm + mt * 16 + h * 8 + erow;
            float brow = (S.bias_mode == 2) ? S.bias[gm] : 0.f;
            #pragma unroll
            for (int nt = 0; nt < 8; nt++) {
                const int gn = n0 + wn + nt * 8 + ecol;
                float x0 = acc[mt][nt][h * 2 + 0] * S.alpha;
                float x1 = acc[mt][nt][h * 2 + 1] * S.alpha;
                if (S.bias_mode == 1) { x0 += S.bias[gn]; x1 += S.bias[gn + 1]; }
                else if (S.bias_mode == 2) { x0 += brow; x1 += brow; }
                if (S.Cf) {
                    float2 v; v.x = x0; v.y = x1;
                    *(float2*)(S.Cf + bz * S.batC + (size_t)gm * S.ldc + gn) = v;
                } else {
                    __half2 hv = __floats2half2_rn(x0, x1);
                    *(__half2*)(S.Ch + bz * S.batC + (size_t)gm * S.ldc + gn) = hv;
                }
            }
        }
    }

    if (S.smode) {
        __threadfence();
        __syncthreads();
        if (tid == 0) {
            int idx = S.sidx + (S.smode == 2 ? mtile : 0);
            atomicAdd(&g_flags[idx], 1);
        }
    }
}

// ---------------- fused preamble: wvec | tcast | casts | fold | uvvec ----------------
// Block layout (dispatch order = dependency order):
//   [0,256)        wvec partials: 2 mats x 4 colgroups x 32 dchunks -> signal f67
//   [256]          cc = bq.bk -> signal f67
//   [257,2305)     tcast Wq/Wk -> WqT/WkT
//   [2305,3329)    cast Wv -> Wvh
//   [3329,11521)   cast h -> hh (one row per block) -> signal f66
//   [11521,11529)  fold partials -> g_w1/g_w2 (waits f67>=257) -> signal f65
//   [11529,12553)  uvvec: 8 rows/block (waits f65>=8 && f66>=8192)
__global__ __launch_bounds__(256) void prep(
    const float* __restrict__ h,
    const float* __restrict__ Wq, const float* __restrict__ Wk,
    const float* __restrict__ Wv,
    const float* __restrict__ bq, const float* __restrict__ bk)
{
    __shared__ __half tile[32][33];
    __shared__ float red[8];
    const int tid = threadIdx.x;
    const int lane = tid & 31;
    const int warp = tid >> 5;
    int b = (int)blockIdx.x;

    if (b < 257) {
        if (b < 256) {
            const bool isq = b < 128;
            const float* W = isq ? Wq : Wk;
            const float* bb = isq ? bk : bq;
            float* dst = isq ? &g_w1p[0][0] : &g_w2p[0][0];
            int lb = isq ? b : b - 128;
            int c = (lb & 3) * 256 + tid;
            int dchunk = lb >> 2;                 // 0..31
            float s = 0.f;
            #pragma unroll 8
            for (int d = dchunk * 32; d < dchunk * 32 + 32; d++)
                s += W[(size_t)d * C_ + c] * bb[d];
            dst[dchunk * C_ + c] = s;
        } else {
            float s = 0.f;
            for (int d = tid; d < C_; d += 256) s += bq[d] * bk[d];
            #pragma unroll
            for (int off = 16; off > 0; off >>= 1)
                s += __shfl_xor_sync(0xffffffffu, s, off);
            if (lane == 0) red[warp] = s;
            __syncthreads();
            if (tid == 0) {
                float t = 0.f;
                for (int w = 0; w < 8; w++) t += red[w];
                g_cc = t;
            }
        }
        __threadfence();
        __syncthreads();
        if (tid == 0) atomicAdd(&g_flags[67], 1);
        return;
    }
    b -= 257;
    if (b < 2048) {   // tcast Wq/Wk
        const int z = b >> 10;
        const int rem = b & 1023;
        const int by = (rem >> 5) * 32;
        const int bx = (rem & 31) * 32;
        const float* in = z ? Wk : Wq;
        __half* out = z ? g_WkT : g_WqT;
        const int tx = tid & 31;
        const int ty = tid >> 5;
        #pragma unroll
        for (int i = 0; i < 32; i += 8)
            tile[ty + i][tx] = __float2half(in[(size_t)(by + ty + i) * C_ + bx + tx]);
        __syncthreads();
        #pragma unroll
        for (int i = 0; i < 32; i += 8)
            out[(size_t)(bx + ty + i) * C_ + by + tx] = tile[tx][ty + i];
        return;
    }
    b -= 2048;
    if (b < 1024) {   // cast Wv
        size_t i = (size_t)b * 256 + tid;
        float4 v = ((const float4*)Wv)[i];
        __half2 h0 = __floats2half2_rn(v.x, v.y);
        __half2 h1 = __floats2half2_rn(v.z, v.w);
        uint2 u;
        u.x = *(uint32_t*)&h0;
        u.y = *(uint32_t*)&h1;
        ((uint2*)g_Wvh)[i] = u;
        return;
    }
    b -= 1024;
    if (b < 8192) {   // cast h (one 1024-elem row per block)
        size_t i = (size_t)b * 256 + tid;
        float4 v = ((const float4*)h)[i];
        __half2 h0 = __floats2half2_rn(v.x, v.y);
        __half2 h1 = __floats2half2_rn(v.z, v.w);
        uint2 u;
        u.x = *(uint32_t*)&h0;
        u.y = *(uint32_t*)&h1;
        ((uint2*)g_hh)[i] = u;
        __threadfence();
        __syncthreads();
        if (tid == 0) atomicAdd(&g_flags[66], 1);
        return;
    }
    b -= 8192;
    if (b < 8) {      // fold 32 partials
        if (tid == 0) spin_ge(&g_flags[67], 257);
        __syncthreads();
        const bool is1 = b < 4;
        const float* src = is1 ? &g_w1p[0][0] : &g_w2p[0][0];
        float* dst = is1 ? g_w1 : g_w2;
        int c = ((is1 ? b : b - 4) & 3) * 256 + tid;
        float sum = 0.f;
        #pragma unroll
        for (int p = 0; p < 32; p++) sum += src[p * C_ + c];
        dst[c] = sum;
        __threadfence();
        __syncthreads();
        if (tid == 0) atomicAdd(&g_flags[65], 1);
        return;
    }
    b -= 8;
    // uvvec: 8 rows per block
    if (tid == 0) { spin_ge(&g_flags[65], 8); spin_ge(&g_flags[66], 8192); }
    __syncthreads();
    __shared__ float w1s[C_], w2s[C_];
    for (int i = tid; i < C_; i += 256) { w1s[i] = g_w1[i]; w2s[i] = g_w2[i]; }
    __syncthreads();
    const int row = b * 8 + warp;
    const __half2* hr = (const __half2*)(g_hh + (size_t)row * C_);
    float s1 = 0.f, s2 = 0.f;
    #pragma unroll
    for (int k = 0; k < 16; k++) {
        int idx = lane + k * 32;
        float2 fv = __half22float2(hr[idx]);
        s1 += fv.x * w1s[2 * idx] + fv.y * w1s[2 * idx + 1];
        s2 += fv.x * w2s[2 * idx] + fv.y * w2s[2 * idx + 1];
    }
    #pragma unroll
    for (int off = 16; off > 0; off >>= 1) {
        s1 += __shfl_xor_sync(0xffffffffu, s1, off);
        s2 += __shfl_xor_sync(0xffffffffu, s2, off);
    }
    if (lane == 0) {
        g_u32[row] = (s1 + g_cc) * (1.0f / 32.0f);
        g_v32[row] = s2 * (1.0f / 32.0f);
    }
}

// ---------------- softmax ----------------
__global__ __launch_bounds__(256) void softmax_h(
    float* __restrict__ P, __half* __restrict__ Ph)
{
    const size_t row = blockIdx.x;
    float* p = P + row * (size_t)N_;
    __half* ph = Ph + row * (size_t)N_;
    const float* vb = g_v32 + (row >> 11 << 11);
    const float uadd = g_u32[row];
    const int tid = threadIdx.x;
    const int lane = tid & 31;
    const int warp = tid >> 5;

    float vals[8];
    float m = -INFINITY;
    #pragma unroll
    for (int i = 0; i < 8; i++) {
        int j = tid + i * 256;
        vals[i] = p[j] + uadd + vb[j];
        m = fmaxf(m, vals[i]);
    }
    __shared__ float redmax[8], redsum[8];
    #pragma unroll
    for (int off = 16; off > 0; off >>= 1)
        m = fmaxf(m, __shfl_xor_sync(0xffffffffu, m, off));
    if (lane == 0) redmax[warp] = m;
    __syncthreads();
    float rowmax = redmax[0];
    #pragma unroll
    for (int w = 1; w < 8; w++) rowmax = fmaxf(rowmax, redmax[w]);

    float sum = 0.f;
    #pragma unroll
    for (int i = 0; i < 8; i++) {
        vals[i] = __expf(vals[i] - rowmax);
        sum += vals[i];
    }
    #pragma unroll
    for (int off = 16; off > 0; off >>= 1)
        sum += __shfl_xor_sync(0xffffffffu, sum, off);
    if (lane == 0) redsum[warp] = sum;
    __syncthreads();
    float total = 0.f;
    #pragma unroll
    for (int w = 0; w < 8; w++) total += redsum[w];
    float inv = 1.f / total;

    #pragma unroll
    for (int i = 0; i < 8; i++) {
        float v = vals[i] * inv;
        p[tid + i * 256] = v;
        ph[tid + i * 256] = __float2half(v);
    }
}

// ---------------- launch ----------------
extern "C" void kernel_launch(void* const* d_in, const int* in_sizes, int n_in,
                              void* d_out, int out_size)
{
    const float* h  = (const float*)d_in[0];
    const float* Wq = (const float*)d_in[1];
    const float* bq = (const float*)d_in[2];
    const float* Wk = (const float*)d_in[3];
    const float* bk = (const float*)d_in[4];
    const float* Wv = (const float*)d_in[5];
    const float* bv = (const float*)d_in[6];

    float* out  = (float*)d_out;
    float* attn = out + (size_t)B_ * N_ * C_;

    __half *hh, *Wvh, *WqT, *WkT, *MT, *QM, *VT, *P;
    cudaGetSymbolAddress((void**)&hh,  g_hh);
    cudaGetSymbolAddress((void**)&Wvh, g_Wvh);
    cudaGetSymbolAddress((void**)&WqT, g_WqT);
    cudaGetSymbolAddress((void**)&WkT, g_WkT);
    cudaGetSymbolAddress((void**)&MT,  g_MT);
    cudaGetSymbolAddress((void**)&QM,  g_QM);
    cudaGetSymbolAddress((void**)&VT,  g_VT);
    cudaGetSymbolAddress((void**)&P,   g_P);

    cudaFuncSetAttribute(gemm_seg4, cudaFuncAttributeMaxDynamicSharedMemorySize, SMEM_GEMM);

    // 1) fused preamble (flags were zeroed by last replay's PV launch; zero at static init)
    prep<<<12553, 256>>>(h, Wq, Wk, Wv, bq, bk);

    auto mkseg = [](const __half* A, const __half* B, long long bA, long long bB,
                    long long bC, int lda, int ldb, int ldc, int K,
                    float* Cf, __half* Ch, float alpha,
                    const float* bias, int bias_mode, int gx, int gy,
                    int wmode, int widx, int wtarget, int smode, int sidx, int zflag) {
        GemmSeg s;
        s.A = A; s.B = B; s.batA = bA; s.batB = bB; s.batC = bC;
        s.lda = lda; s.ldb = ldb; s.ldc = ldc; s.K = K;
        s.Cf = Cf; s.Ch = Ch; s.alpha = alpha; s.bias = bias; s.bias_mode = bias_mode;
        s.gx = gx; s.gxy = gx * gy;
        s.wmode = wmode; s.widx = widx; s.wtarget = wtarget;
        s.smode = smode; s.sidx = sidx; s.zflag = zflag;
        return s;
    };

    // 2) MEGA GEMM launch: MT -> flags[0]; VT; QM waits f0>=32 -> flags[1+mtile];
    //    scores waits flags[1+mtile]>=4.
    {
        GemmSeg sMT = mkseg(WkT, WqT, 0, 0, 0, C_, C_, C_, C_,
                            nullptr, MT, 1.0f, nullptr, 0, C_ / BN_, C_ / BM_,
                            0, 0, 0, 1, 0, 0);
        GemmSeg sVT = mkseg(Wvh, hh, 0, 0, 0, C_, C_, M_TOT, C_,
                            nullptr, VT, 1.0f, bv, 2, M_TOT / BN_, C_ / BM_,
                            0, 0, 0, 0, 0, 0);
        GemmSeg sQM = mkseg(hh, MT, 0, 0, 0, C_, C_, C_, C_,
                            nullptr, QM, 1.0f, nullptr, 0, C_ / BN_, M_TOT / BM_,
                            1, 0, 32, 2, 1, 0);
        GemmSeg sSC = mkseg(QM, hh, (long long)N_ * C_, (long long)N_ * C_,
                            (long long)N_ * N_, C_, C_, N_, C_,
                            attn, nullptr, 1.0f / 32.0f, nullptr, 0, N_ / BN_, N_ / BM_,
                            2, 1, 4, 0, 0, 0);
        int nMT = 32, nVT = 256, nQM = 256, nSC = 512;
        int e0 = nMT, e1 = e0 + nVT, e2 = e1 + nQM;
        gemm_seg4<<<e2 + nSC, 256, SMEM_GEMM>>>(sMT, sVT, sQM, sSC, e0, e1, e2);
    }
    // 3) softmax + fp16 P
    softmax_h<<<B_ * N_, 256>>>(attn, P);

    // 4) out = P_b @ VT_b^T  [256 CTAs]; block 0 resets flags for next replay
    {
        GemmSeg s = mkseg(P, VT, (long long)N_ * N_, (long long)N_,
                          (long long)N_ * C_, N_, M_TOT, C_, N_,
                          out, nullptr, 1.0f, nullptr, 0, C_ / BN_, N_ / BM_,
                          0, 0, 0, 0, 0, 1);
        int n = s.gxy * B_;
        gemm_seg4<<<n, 256, SMEM_GEMM>>>(s, s, s, s, n, n, n);
    }
}

// round 16
// speedup vs baseline: 1.1443x; 1.0093x over previous
#include <cuda_runtime.h>
#include <cuda_fp16.h>
#include <math.h>
#include <stdint.h>

#define B_ 4
#define N_ 2048
#define C_ 1024
#define M_TOT (B_ * N_)   // 8192

// ---------------- scratch (__device__ globals; no allocation) ----------------
__device__ __align__(128) __half g_hh[(size_t)M_TOT * C_];
__device__ __align__(128) __half g_Wvh[C_ * C_];
__device__ __align__(128) __half g_WqT[C_ * C_];
__device__ __align__(128) __half g_WkT[C_ * C_];
__device__ __align__(128) __half g_MT[C_ * C_];
__device__ __align__(128) __half g_QM[(size_t)M_TOT * C_];
__device__ __align__(128) __half g_VT[(size_t)C_ * M_TOT];
__device__ __align__(128) __half g_P[(size_t)B_ * N_ * N_];
__device__ float g_w1p[32][C_], g_w2p[32][C_];
__device__ float g_w1[C_], g_w2[C_];
__device__ float g_u32[M_TOT], g_v32[M_TOT];
__device__ float g_cc;
// flags: [0]=MT done (64); [1..64]=QM per-m-tile (8 each); [65]=fold (8);
//        [66]=h-cast blocks (8192); [67]=wvec partial blocks (257)
__device__ int g_flags[80];

// ---------------- portable PTX helpers ----------------
__device__ __forceinline__ uint32_t smem_u32(const void* p) {
    uint32_t a;
    asm("{ .reg .u64 t; cvta.to.shared.u64 t, %1; cvt.u32.u64 %0, t; }" : "=r"(a) : "l"(p));
    return a;
}
__device__ __forceinline__ void cp_async16(uint32_t dst, const void* src) {
    asm volatile("cp.async.cg.shared.global [%0], [%1], 16;" :: "r"(dst), "l"(src) : "memory");
}
#define CP_COMMIT()  asm volatile("cp.async.commit_group;" ::: "memory")
#define CP_WAIT(n)   asm volatile("cp.async.wait_group %0;" :: "n"(n) : "memory")

__device__ __forceinline__ void ldsm_x4(uint32_t& r0, uint32_t& r1, uint32_t& r2, uint32_t& r3,
                                        uint32_t addr) {
    asm volatile("ldmatrix.sync.aligned.m8n8.x4.shared.b16 {%0,%1,%2,%3}, [%4];"
                 : "=r"(r0), "=r"(r1), "=r"(r2), "=r"(r3) : "r"(addr));
}
__device__ __forceinline__ void mma16816(float* d, const uint32_t* a, const uint32_t* b) {
    asm volatile(
        "mma.sync.aligned.m16n8k16.row.col.f32.f16.f16.f32 "
        "{%0,%1,%2,%3}, {%4,%5,%6,%7}, {%8,%9}, {%0,%1,%2,%3};"
        : "+f"(d[0]), "+f"(d[1]), "+f"(d[2]), "+f"(d[3])
        : "r"(a[0]), "r"(a[1]), "r"(a[2]), "r"(a[3]), "r"(b[0]), "r"(b[1]));
}
__device__ __forceinline__ uint32_t swz(uint32_t off) { return off ^ ((off >> 3) & 0x70); }

__device__ __forceinline__ int ld_acq(const int* p) {
    int v;
    asm volatile("ld.acquire.gpu.global.s32 %0, [%1];" : "=r"(v) : "l"(p));
    return v;
}
__device__ __forceinline__ void spin_ge(const int* p, int target) {
    while (ld_acq(p) < target) { __nanosleep(64); }
}

// ---------------- segmented fp16 GEMM: 128x128 tiles, 2 CTAs/SM ----------------
// 8 warps 2(m)x4(n), warp tile 64x32. BK=64 (128B rows).
#define BM_ 128
#define BN_ 128
#define STAGES 3
#define TILE_A_BYTES 16384
#define STAGE_BYTES  32768           // A + B (128 rows each)
#define SMEM_GEMM (STAGES * STAGE_BYTES)   // 96 KB

struct GemmSeg {
    const __half* A; const __half* B;
    long long batA, batB, batC;
    int lda, ldb, ldc, K;
    float* Cf; __half* Ch;
    float alpha;
    const float* bias; int bias_mode;
    int gx, gxy;
    int wmode, widx, wtarget;
    int smode, sidx;
    int zflag;
};

__global__ __launch_bounds__(256, 2) void gemm_seg4(
    GemmSeg s0, GemmSeg s1, GemmSeg s2, GemmSeg s3, int e0, int e1, int e2)
{
    extern __shared__ char smem[];
    const uint32_t sbase = smem_u32(smem);
    const int tid  = threadIdx.x;
    const int wid  = tid >> 5;
    const int lane = tid & 31;

    GemmSeg S;
    int lid;
    {
        const int bi = (int)blockIdx.x;
        if (bi < e0)      { S = s0; lid = bi; }
        else if (bi < e1) { S = s1; lid = bi - e0; }
        else if (bi < e2) { S = s2; lid = bi - e1; }
        else              { S = s3; lid = bi - e2; }
    }

    if (S.zflag && lid == 0 && tid < 80) g_flags[tid] = 0;

    const long long bz = lid / S.gxy;
    int r = lid - (int)bz * S.gxy;
    const int m0 = (r / S.gx) * BM_;
    const int n0 = (r % S.gx) * BN_;
    const int gy = S.gxy / S.gx;
    const int mtile = (int)bz * gy + m0 / BM_;

    if (S.wmode) {
        int idx = S.widx + (S.wmode == 2 ? mtile : 0);
        if (tid == 0) spin_ge(&g_flags[idx], S.wtarget);
        __syncthreads();
    }

    const __half* Ap = S.A + bz * S.batA;
    const __half* Bp = S.B + bz * S.batB;

    const int wm = (wid >> 2) * 64;
    const int wn = (wid & 3) * 32;

    const int NK = S.K >> 6;
    const int lda = S.lda, ldb = S.ldb;

    const int lrow = tid >> 3;
    const int lch  = tid & 7;

    auto load_stage = [&](int kc, int s) {
        const __half* Asrc = Ap + (size_t)m0 * lda + kc * 64;
        const __half* Bsrc = Bp + (size_t)n0 * ldb + kc * 64;
        const uint32_t sa = sbase + s * STAGE_BYTES;
        const uint32_t sb = sa + TILE_A_BYTES;
        #pragma unroll
        for (int rr = 0; rr < 4; rr++) {
            int row = rr * 32 + lrow;
            uint32_t sw = swz(row * 128 + lch * 16);
            cp_async16(sa + sw, Asrc + (size_t)row * lda + lch * 8);
        }
        #pragma unroll
        for (int rr = 0; rr < 4; rr++) {
            int row = rr * 32 + lrow;
            uint32_t sw = swz(row * 128 + lch * 16);
            cp_async16(sb + sw, Bsrc + (size_t)row * ldb + lch * 8);
        }
        CP_COMMIT();
    };

    float acc[4][4][4];
    #pragma unroll
    for (int i = 0; i < 4; i++)
        #pragma unroll
        for (int j = 0; j < 4; j++)
            #pragma unroll
            for (int e = 0; e < 4; e++) acc[i][j][e] = 0.f;

    const int a_row_l = ((lane >> 3) & 1) * 8 + (lane & 7);
    const int a_col_l = ((lane >> 4) & 1) * 16;
    const int b_row_l = ((lane >> 4) & 1) * 8 + (lane & 7);
    const int b_col_l = ((lane >> 3) & 1) * 16;

    #pragma unroll
    for (int i = 0; i < STAGES; i++)
        if (i < NK) load_stage(i, i);

    int s = 0;
    for (int kc = 0; kc < NK; kc++) {
        int rem = NK - 1 - kc;
        if (rem >= 2)      { CP_WAIT(2); }
        else if (rem == 1) { CP_WAIT(1); }
        else               { CP_WAIT(0); }
        __syncthreads();

        const uint32_t cur_sa = sbase + s * STAGE_BYTES;
        const uint32_t cur_sb = cur_sa + TILE_A_BYTES;

        #pragma unroll
        for (int k16 = 0; k16 < 4; k16++) {
            uint32_t a[4][4], b[4][2];
            #pragma unroll
            for (int mt = 0; mt < 4; mt++) {
                uint32_t off = (uint32_t)(wm + mt * 16 + a_row_l) * 128 + k16 * 32 + a_col_l;
                ldsm_x4(a[mt][0], a[mt][1], a[mt][2], a[mt][3], cur_sa + swz(off));
            }
            #pragma unroll
            for (int nt2 = 0; nt2 < 2; nt2++) {
                uint32_t off = (uint32_t)(wn + nt2 * 16 + b_row_l) * 128 + k16 * 32 + b_col_l;
                uint32_t r0, r1, r2, r3;
                ldsm_x4(r0, r1, r2, r3, cur_sb + swz(off));
                b[nt2 * 2 + 0][0] = r0; b[nt2 * 2 + 0][1] = r1;
                b[nt2 * 2 + 1][0] = r2; b[nt2 * 2 + 1][1] = r3;
            }
            #pragma unroll
            for (int mt = 0; mt < 4; mt++)
                #pragma unroll
                for (int nt = 0; nt < 4; nt++)
                    mma16816(acc[mt][nt], a[mt], b[nt]);
        }

        __syncthreads();
        if (kc + STAGES < NK) load_stage(kc + STAGES, s);
        s++;
        if (s == STAGES) s = 0;
    }

    const int erow = lane >> 2;
    const int ecol = (lane & 3) * 2;

    #pragma unroll
    for (int mt = 0; mt < 4; mt++) {
        #pragma unroll
        for (int h = 0; h < 2; h++) {
            const int gm = m0 + wm + mt * 16 + h * 8 + erow;
            float brow = (S.bias_mode == 2) ? S.bias[gm] : 0.f;
            #pragma unroll
            for (int nt = 0; nt < 4; nt++) {
                const int gn = n0 + wn + nt * 8 + ecol;
                float x0 = acc[mt][nt][h * 2 + 0] * S.alpha;
                float x1 = acc[mt][nt][h * 2 + 1] * S.alpha;
                if (S.bias_mode == 1) { x0 += S.bias[gn]; x1 += S.bias[gn + 1]; }
                else if (S.bias_mode == 2) { x0 += brow; x1 += brow; }
                if (S.Cf) {
                    float2 v; v.x = x0; v.y = x1;
                    *(float2*)(S.Cf + bz * S.batC + (size_t)gm * S.ldc + gn) = v;
                } else {
                    __half2 hv = __floats2half2_rn(x0, x1);
                    *(__half2*)(S.Ch + bz * S.batC + (size_t)gm * S.ldc + gn) = hv;
                }
            }
        }
    }

    if (S.smode) {
        __threadfence();
        __syncthreads();
        if (tid == 0) {
            int idx = S.sidx + (S.smode == 2 ? mtile : 0);
            atomicAdd(&g_flags[idx], 1);
        }
    }
}

// ---------------- fused preamble (unchanged from R15) ----------------
__global__ __launch_bounds__(256) void prep(
    const float* __restrict__ h,
    const float* __restrict__ Wq, const float* __restrict__ Wk,
    const float* __restrict__ Wv,
    const float* __restrict__ bq, const float* __restrict__ bk)
{
    __shared__ __half tile[32][33];
    __shared__ float red[8];
    const int tid = threadIdx.x;
    const int lane = tid & 31;
    const int warp = tid >> 5;
    int b = (int)blockIdx.x;

    if (b < 257) {
        if (b < 256) {
            const bool isq = b < 128;
            const float* W = isq ? Wq : Wk;
            const float* bb = isq ? bk : bq;
            float* dst = isq ? &g_w1p[0][0] : &g_w2p[0][0];
            int lb = isq ? b : b - 128;
            int c = (lb & 3) * 256 + tid;
            int dchunk = lb >> 2;
            float s = 0.f;
            #pragma unroll 8
            for (int d = dchunk * 32; d < dchunk * 32 + 32; d++)
                s += W[(size_t)d * C_ + c] * bb[d];
            dst[dchunk * C_ + c] = s;
        } else {
            float s = 0.f;
            for (int d = tid; d < C_; d += 256) s += bq[d] * bk[d];
            #pragma unroll
            for (int off = 16; off > 0; off >>= 1)
                s += __shfl_xor_sync(0xffffffffu, s, off);
            if (lane == 0) red[warp] = s;
            __syncthreads();
            if (tid == 0) {
                float t = 0.f;
                for (int w = 0; w < 8; w++) t += red[w];
                g_cc = t;
            }
        }
        __threadfence();
        __syncthreads();
        if (tid == 0) atomicAdd(&g_flags[67], 1);
        return;
    }
    b -= 257;
    if (b < 2048) {
        const int z = b >> 10;
        const int rem = b & 1023;
        const int by = (rem >> 5) * 32;
        const int bx = (rem & 31) * 32;
        const float* in = z ? Wk : Wq;
        __half* out = z ? g_WkT : g_WqT;
        const int tx = tid & 31;
        const int ty = tid >> 5;
        #pragma unroll
        for (int i = 0; i < 32; i += 8)
            tile[ty + i][tx] = __float2half(in[(size_t)(by + ty + i) * C_ + bx + tx]);
        __syncthreads();
        #pragma unroll
        for (int i = 0; i < 32; i += 8)
            out[(size_t)(bx + ty + i) * C_ + by + tx] = tile[tx][ty + i];
        return;
    }
    b -= 2048;
    if (b < 1024) {
        size_t i = (size_t)b * 256 + tid;
        float4 v = ((const float4*)Wv)[i];
        __half2 h0 = __floats2half2_rn(v.x, v.y);
        __half2 h1 = __floats2half2_rn(v.z, v.w);
        uint2 u;
        u.x = *(uint32_t*)&h0;
        u.y = *(uint32_t*)&h1;
        ((uint2*)g_Wvh)[i] = u;
        return;
    }
    b -= 1024;
    if (b < 8192) {
        size_t i = (size_t)b * 256 + tid;
        float4 v = ((const float4*)h)[i];
        __half2 h0 = __floats2half2_rn(v.x, v.y);
        __half2 h1 = __floats2half2_rn(v.z, v.w);
        uint2 u;
        u.x = *(uint32_t*)&h0;
        u.y = *(uint32_t*)&h1;
        ((uint2*)g_hh)[i] = u;
        __threadfence();
        __syncthreads();
        if (tid == 0) atomicAdd(&g_flags[66], 1);
        return;
    }
    b -= 8192;
    if (b < 8) {
        if (tid == 0) spin_ge(&g_flags[67], 257);
        __syncthreads();
        const bool is1 = b < 4;
        const float* src = is1 ? &g_w1p[0][0] : &g_w2p[0][0];
        float* dst = is1 ? g_w1 : g_w2;
        int c = ((is1 ? b : b - 4) & 3) * 256 + tid;
        float sum = 0.f;
        #pragma unroll
        for (int p = 0; p < 32; p++) sum += src[p * C_ + c];
        dst[c] = sum;
        __threadfence();
        __syncthreads();
        if (tid == 0) atomicAdd(&g_flags[65], 1);
        return;
    }
    b -= 8;
    if (tid == 0) { spin_ge(&g_flags[65], 8); spin_ge(&g_flags[66], 8192); }
    __syncthreads();
    __shared__ float w1s[C_], w2s[C_];
    for (int i = tid; i < C_; i += 256) { w1s[i] = g_w1[i]; w2s[i] = g_w2[i]; }
    __syncthreads();
    const int row = b * 8 + warp;
    const __half2* hr = (const __half2*)(g_hh + (size_t)row * C_);
    float s1 = 0.f, s2 = 0.f;
    #pragma unroll
    for (int k = 0; k < 16; k++) {
        int idx = lane + k * 32;
        float2 fv = __half22float2(hr[idx]);
        s1 += fv.x * w1s[2 * idx] + fv.y * w1s[2 * idx + 1];
        s2 += fv.x * w2s[2 * idx] + fv.y * w2s[2 * idx + 1];
    }
    #pragma unroll
    for (int off = 16; off > 0; off >>= 1) {
        s1 += __shfl_xor_sync(0xffffffffu, s1, off);
        s2 += __shfl_xor_sync(0xffffffffu, s2, off);
    }
    if (lane == 0) {
        g_u32[row] = (s1 + g_cc) * (1.0f / 32.0f);
        g_v32[row] = s2 * (1.0f / 32.0f);
    }
}

// ---------------- softmax ----------------
__global__ __launch_bounds__(256) void softmax_h(
    float* __restrict__ P, __half* __restrict__ Ph)
{
    const size_t row = blockIdx.x;
    float* p = P + row * (size_t)N_;
    __half* ph = Ph + row * (size_t)N_;
    const float* vb = g_v32 + (row >> 11 << 11);
    const float uadd = g_u32[row];
    const int tid = threadIdx.x;
    const int lane = tid & 31;
    const int warp = tid >> 5;

    float vals[8];
    float m = -INFINITY;
    #pragma unroll
    for (int i = 0; i < 8; i++) {
        int j = tid + i * 256;
        vals[i] = p[j] + uadd + vb[j];
        m = fmaxf(m, vals[i]);
    }
    __shared__ float redmax[8], redsum[8];
    #pragma unroll
    for (int off = 16; off > 0; off >>= 1)
        m = fmaxf(m, __shfl_xor_sync(0xffffffffu, m, off));
    if (lane == 0) redmax[warp] = m;
    __syncthreads();
    float rowmax = redmax[0];
    #pragma unroll
    for (int w = 1; w < 8; w++) rowmax = fmaxf(rowmax, redmax[w]);

    float sum = 0.f;
    #pragma unroll
    for (int i = 0; i < 8; i++) {
        vals[i] = __expf(vals[i] - rowmax);
        sum += vals[i];
    }
    #pragma unroll
    for (int off = 16; off > 0; off >>= 1)
        sum += __shfl_xor_sync(0xffffffffu, sum, off);
    if (lane == 0) redsum[warp] = sum;
    __syncthreads();
    float total = 0.f;
    #pragma unroll
    for (int w = 0; w < 8; w++) total += redsum[w];
    float inv = 1.f / total;

    #pragma unroll
    for (int i = 0; i < 8; i++) {
        float v = vals[i] * inv;
        p[tid + i * 256] = v;
        ph[tid + i * 256] = __float2half(v);
    }
}

// ---------------- launch ----------------
extern "C" void kernel_launch(void* const* d_in, const int* in_sizes, int n_in,
                              void* d_out, int out_size)
{
    const float* h  = (const float*)d_in[0];
    const float* Wq = (const float*)d_in[1];
    const float* bq = (const float*)d_in[2];
    const float* Wk = (const float*)d_in[3];
    const float* bk = (const float*)d_in[4];
    const float* Wv = (const float*)d_in[5];
    const float* bv = (const float*)d_in[6];

    float* out  = (float*)d_out;
    float* attn = out + (size_t)B_ * N_ * C_;

    __half *hh, *Wvh, *WqT, *WkT, *MT, *QM, *VT, *P;
    cudaGetSymbolAddress((void**)&hh,  g_hh);
    cudaGetSymbolAddress((void**)&Wvh, g_Wvh);
    cudaGetSymbolAddress((void**)&WqT, g_WqT);
    cudaGetSymbolAddress((void**)&WkT, g_WkT);
    cudaGetSymbolAddress((void**)&MT,  g_MT);
    cudaGetSymbolAddress((void**)&QM,  g_QM);
    cudaGetSymbolAddress((void**)&VT,  g_VT);
    cudaGetSymbolAddress((void**)&P,   g_P);

    cudaFuncSetAttribute(gemm_seg4, cudaFuncAttributeMaxDynamicSharedMemorySize, SMEM_GEMM);

    // 1) fused preamble
    prep<<<12553, 256>>>(h, Wq, Wk, Wv, bq, bk);

    auto mkseg = [](const __half* A, const __half* B, long long bA, long long bB,
                    long long bC, int lda, int ldb, int ldc, int K,
                    float* Cf, __half* Ch, float alpha,
                    const float* bias, int bias_mode, int gx, int gy,
                    int wmode, int widx, int wtarget, int smode, int sidx, int zflag) {
        GemmSeg s;
        s.A = A; s.B = B; s.batA = bA; s.batB = bB; s.batC = bC;
        s.lda = lda; s.ldb = ldb; s.ldc = ldc; s.K = K;
        s.Cf = Cf; s.Ch = Ch; s.alpha = alpha; s.bias = bias; s.bias_mode = bias_mode;
        s.gx = gx; s.gxy = gx * gy;
        s.wmode = wmode; s.widx = widx; s.wtarget = wtarget;
        s.smode = smode; s.sidx = sidx; s.zflag = zflag;
        return s;
    };

    // 2) MEGA GEMM: MT(64) -> f0; VT(512); QM(512) waits f0>=64 -> f[1+mtile];
    //    scores(1024) waits f[1+mtile]>=8.
    {
        GemmSeg sMT = mkseg(WkT, WqT, 0, 0, 0, C_, C_, C_, C_,
                            nullptr, MT, 1.0f, nullptr, 0, C_ / BN_, C_ / BM_,
                            0, 0, 0, 1, 0, 0);
        GemmSeg sVT = mkseg(Wvh, hh, 0, 0, 0, C_, C_, M_TOT, C_,
                            nullptr, VT, 1.0f, bv, 2, M_TOT / BN_, C_ / BM_,
                            0, 0, 0, 0, 0, 0);
        GemmSeg sQM = mkseg(hh, MT, 0, 0, 0, C_, C_, C_, C_,
                            nullptr, QM, 1.0f, nullptr, 0, C_ / BN_, M_TOT / BM_,
                            1, 0, 64, 2, 1, 0);
        GemmSeg sSC = mkseg(QM, hh, (long long)N_ * C_, (long long)N_ * C_,
                            (long long)N_ * N_, C_, C_, N_, C_,
                            attn, nullptr, 1.0f / 32.0f, nullptr, 0, N_ / BN_, N_ / BM_,
                            2, 1, 8, 0, 0, 0);
        int nMT = 64, nVT = 512, nQM = 512, nSC = 1024;
        int e0 = nMT, e1 = e0 + nVT, e2 = e1 + nQM;
        gemm_seg4<<<e2 + nSC, 256, SMEM_GEMM>>>(sMT, sVT, sQM, sSC, e0, e1, e2);
    }
    // 3) softmax + fp16 P
    softmax_h<<<B_ * N_, 256>>>(attn, P);

    // 4) out = P_b @ VT_b^T  [512 CTAs]; block 0 resets flags for next replay
    {
        GemmSeg s = mkseg(P, VT, (long long)N_ * N_, (long long)N_,
                          (long long)N_ * C_, N_, M_TOT, C_, N_,
                          out, nullptr, 1.0f, nullptr, 0, C_ / BN_, N_ / BM_,
                          0, 0, 0, 0, 0, 1);
        int n = s.gxy * B_;
        gemm_seg4<<<n, 256, SMEM_GEMM>>>(s, s, s, s, n, n, n);
    }
}